// round 13
// baseline (speedup 1.0000x reference)
#include <cuda_runtime.h>
#include <cuda_fp16.h>
#include <math_constants.h>
#include <cstdint>

// ---------------- problem constants ----------------
#define N_API   50000
#define N_FILE  20000
#define N_INP   512
#define N_OUT   256
#define NH      3
#define HD      768   // NH*N_OUT
#define KAGG    1536  // NH*N_INP
#define M_PAD   20096 // 157*128
#define NCHUNK  48    // KAGG/32 (k-chunk = 32 halfs)

// pipeline chunking: 157 row-blocks = 80 + 77
#define CH0_BLOCKS 80
#define CH1_BLOCKS 77
#define CH0_DST    (CH0_BLOCKS * 128)    // 10240 (div by 8)
#define CH1_DST    (N_FILE - CH0_DST)    // 9760  (div by 8)

#define SCAN_BLOCKS ((N_FILE + 511) / 512)   // 40

// ---------------- device scratch ----------------
__device__ float  d_Wcomb[N_INP * HD];
__device__ float  d_W2   [KAGG * N_OUT];
__device__ __half d_W2Th [N_OUT * KAGG];
__device__ __half d_embh [(size_t)N_API * N_INP];   // fp16 emb_api
__device__ __half d_aggh [(size_t)M_PAD * KAGG];    // fp16 agg (tail rows stay 0)
__device__ float  d_u    [N_INP * NH];
__device__ float  d_vli  [N_INP * NH];
__device__ float  d_Vl   [N_INP * NH];
__device__ float  d_Vr   [N_INP * NH];
__device__ float  d_bsrc [HD];
__device__ float  d_bl   [NH];
__device__ float  d_br   [NH];
__device__ float  d_bconst[N_OUT];
__device__ float  d_cbias [N_OUT];
__device__ float  d_el   [N_API * 4];
__device__ float  d_er   [N_FILE * 4];
__device__ int    d_deg  [N_FILE];
__device__ int    d_cur  [N_FILE];
__device__ int    d_off  [N_FILE + 1];
__device__ int    d_bsum [SCAN_BLOCKS];
__device__ int    d_bbase[SCAN_BLOCKS];
__device__ float  d_hasedge[N_FILE];
__device__ int    d_srcs [262144];

// ---------------- helpers ----------------
__device__ __forceinline__ uint32_t smem_u32(const void* p) {
    uint32_t a;
    asm("{ .reg .u64 t; cvta.to.shared.u64 t, %1; cvt.u32.u64 %0, t; }" : "=r"(a) : "l"(p));
    return a;
}
__device__ __forceinline__ float lrelu(float v) { return v > 0.f ? v : 0.2f * v; }

#define CP_ASYNC16(dst, src) \
    asm volatile("cp.async.cg.shared.global [%0], [%1], 16;" :: "r"(dst), "l"(src) : "memory")
#define CP_COMMIT()  asm volatile("cp.async.commit_group;" ::: "memory")
#define CP_WAIT0()   asm volatile("cp.async.wait_group 0;" ::: "memory")
#define CP_WAIT1()   asm volatile("cp.async.wait_group 1;" ::: "memory")

#define LDSM_X4(r0, r1, r2, r3, addr) \
    asm volatile("ldmatrix.sync.aligned.m8n8.x4.shared.b16 {%0,%1,%2,%3}, [%4];" \
                 : "=r"(r0), "=r"(r1), "=r"(r2), "=r"(r3) : "r"(addr))

__device__ __forceinline__ void mma_f16(float* c, const uint32_t* a, const uint32_t* b) {
    asm volatile(
        "mma.sync.aligned.m16n8k16.row.col.f32.f16.f16.f32 "
        "{%0,%1,%2,%3}, {%4,%5,%6,%7}, {%8,%9}, {%0,%1,%2,%3};"
        : "+f"(c[0]), "+f"(c[1]), "+f"(c[2]), "+f"(c[3])
        : "r"(a[0]), "r"(a[1]), "r"(a[2]), "r"(a[3]), "r"(b[0]), "r"(b[1]));
}

// ---------------- fp16 tensor-core GEMM with ldmatrix fragments ----------------
#define LDPH   40
#define TILEH  (128 * LDPH)
#define GEMM_SMEM_BYTES (4 * TILEH * 2)

__global__ void __launch_bounds__(256, 2)
gemm_mma(const __half* __restrict__ A, const __half* __restrict__ B,
         float* __restrict__ C,
         const float* __restrict__ cbias,
         const float* __restrict__ bconst,
         const float* __restrict__ hasedge,
         int mb_base)
{
    extern __shared__ __half smh[];
    __half* As = smh;
    __half* Bs = smh + 2 * TILEH;

    const int tid  = threadIdx.x;
    const int wid  = tid >> 5, lane = tid & 31;
    const int wm   = wid & 1;
    const int wn   = wid >> 1;
    const int m0   = (mb_base + blockIdx.y) * 128;
    const int n0   = blockIdx.x * 128;

    const uint32_t As_u = smem_u32(As);
    const uint32_t Bs_u = smem_u32(Bs);

    const uint32_t aOff = (uint32_t)(((wm * 64 + (lane & 15)) * LDPH + (lane >> 4) * 8) * 2);
    const uint32_t bOff = (uint32_t)(((wn * 32 + (lane & 7) + (lane >> 4) * 8) * LDPH
                                      + ((lane >> 3) & 1) * 8) * 2);

    float acc[4][4][4];
#pragma unroll
    for (int a = 0; a < 4; a++)
#pragma unroll
        for (int b = 0; b < 4; b++)
#pragma unroll
            for (int c = 0; c < 4; c++) acc[a][b][c] = 0.f;

#define LOAD_TILE(kt, s) do {                                                     \
    int _k0 = (kt) * 32;                                                          \
    _Pragma("unroll")                                                             \
    for (int _t = 0; _t < 2; _t++) {                                              \
        int _idx = tid + _t * 256;                                                \
        int _row = _idx >> 2, _seg = _idx & 3;                                    \
        const __half* _g = A + (size_t)(m0 + _row) * KAGG + _k0 + _seg * 8;       \
        CP_ASYNC16(As_u + (uint32_t)(((s) * TILEH + _row * LDPH + _seg * 8) * 2), _g); \
    }                                                                             \
    _Pragma("unroll")                                                             \
    for (int _t = 0; _t < 2; _t++) {                                              \
        int _idx = tid + _t * 256;                                                \
        int _row = _idx >> 2, _seg = _idx & 3;                                    \
        const __half* _g = B + (size_t)(n0 + _row) * KAGG + _k0 + _seg * 8;       \
        CP_ASYNC16(Bs_u + (uint32_t)(((s) * TILEH + _row * LDPH + _seg * 8) * 2), _g); \
    }                                                                             \
    CP_COMMIT();                                                                  \
} while (0)

    LOAD_TILE(0, 0);

    for (int kt = 0; kt < NCHUNK; kt++) {
        int s = kt & 1;
        if (kt + 1 < NCHUNK) { LOAD_TILE(kt + 1, s ^ 1); CP_WAIT1(); }
        else                 { CP_WAIT0(); }
        __syncthreads();

        const uint32_t aBase = As_u + (uint32_t)(s * TILEH * 2) + aOff;
        const uint32_t bBase = Bs_u + (uint32_t)(s * TILEH * 2) + bOff;

#pragma unroll
        for (int ks = 0; ks < 2; ks++) {
            const uint32_t kByte = (uint32_t)(ks * 32);
            uint32_t afr[4][4];
#pragma unroll
            for (int mi = 0; mi < 4; mi++)
                LDSM_X4(afr[mi][0], afr[mi][1], afr[mi][2], afr[mi][3],
                        aBase + (uint32_t)(mi * 16 * LDPH * 2) + kByte);
            uint32_t bfr[4][2];
#pragma unroll
            for (int nj = 0; nj < 2; nj++)
                LDSM_X4(bfr[nj * 2][0], bfr[nj * 2][1], bfr[nj * 2 + 1][0], bfr[nj * 2 + 1][1],
                        bBase + (uint32_t)(nj * 16 * LDPH * 2) + kByte);
#pragma unroll
            for (int mi = 0; mi < 4; mi++)
#pragma unroll
                for (int ni = 0; ni < 4; ni++)
                    mma_f16(acc[mi][ni], afr[mi], bfr[ni]);
        }
        __syncthreads();
    }

#pragma unroll
    for (int mi = 0; mi < 4; mi++) {
        int rbase = m0 + wm * 64 + mi * 16 + (lane >> 2);
#pragma unroll
        for (int half_ = 0; half_ < 2; half_++) {
            int r = rbase + half_ * 8;
            if (r >= N_FILE) continue;
            float he = hasedge[r];
#pragma unroll
            for (int ni = 0; ni < 4; ni++) {
                int c0 = n0 + wn * 32 + ni * 8 + (lane & 3) * 2;
                float v0 = acc[mi][ni][half_ * 2 + 0] + cbias[c0]     + he * bconst[c0];
                float v1 = acc[mi][ni][half_ * 2 + 1] + cbias[c0 + 1] + he * bconst[c0 + 1];
                *(float2*)(C + (size_t)r * N_OUT + c0) = make_float2(v0, v1);
            }
        }
    }
}

// ---------------- fp32 SGEMM (precompute-sized, batched z) ----
#define BM 128
#define BN 128
#define BK 8
#define TM 8
#define TN 8

__global__ __launch_bounds__(256, 2)
void sgemm(const float* __restrict__ A, int lda,
           const float* __restrict__ B, int ldb,
           float* __restrict__ C, int ldc,
           int M, int N, int K,
           long sA, long sB, long sC)
{
    A += (long)blockIdx.z * sA;
    B += (long)blockIdx.z * sB;
    C += (long)blockIdx.z * sC;

    __shared__ float As[BK][BM];
    __shared__ float Bs[BK][BN];
    const int tid = threadIdx.x;
    const int bm  = blockIdx.y * BM;
    const int bn  = blockIdx.x * BN;

    const int aRow  = tid >> 1;
    const int aCol4 = (tid & 1) * 4;
    const int bRow  = tid >> 5;
    const int bCol4 = (tid & 31) * 4;
    const int ty = tid >> 4, tx = tid & 15;

    float acc[TM][TN];
#pragma unroll
    for (int i = 0; i < TM; i++)
#pragma unroll
        for (int j = 0; j < TN; j++) acc[i][j] = 0.f;

    for (int k0 = 0; k0 < K; k0 += BK) {
        float4 av;
        if (bm + aRow < M)
            av = *(const float4*)(A + (size_t)(bm + aRow) * lda + k0 + aCol4);
        else
            av = make_float4(0.f, 0.f, 0.f, 0.f);
        As[aCol4 + 0][aRow] = av.x;
        As[aCol4 + 1][aRow] = av.y;
        As[aCol4 + 2][aRow] = av.z;
        As[aCol4 + 3][aRow] = av.w;

        float4 bv = *(const float4*)(B + (size_t)(k0 + bRow) * ldb + bn + bCol4);
        *(float4*)(&Bs[bRow][bCol4]) = bv;

        __syncthreads();
#pragma unroll
        for (int k = 0; k < BK; k++) {
            float ra[TM], rb[TN];
#pragma unroll
            for (int i = 0; i < TM; i++) ra[i] = As[k][ty * TM + i];
#pragma unroll
            for (int j = 0; j < TN; j++) rb[j] = Bs[k][tx * TN + j];
#pragma unroll
            for (int i = 0; i < TM; i++)
#pragma unroll
                for (int j = 0; j < TN; j++)
                    acc[i][j] = fmaf(ra[i], rb[j], acc[i][j]);
        }
        __syncthreads();
    }

#pragma unroll
    for (int i = 0; i < TM; i++) {
        int row = bm + ty * TM + i;
        if (row >= M) break;
#pragma unroll
        for (int j = 0; j < TN; j += 4) {
            int col = bn + tx * TN + j;
            float4 v;
            v.x = acc[i][j];     v.y = acc[i][j + 1];
            v.z = acc[i][j + 2]; v.w = acc[i][j + 3];
            *(float4*)(C + (size_t)row * ldc + col) = v;
        }
    }
}

// ---------------- coalesced GEVM ----------
__global__ __launch_bounds__(256)
void gevm(const float* __restrict__ x, const float* __restrict__ W,
          float* __restrict__ y, int K, int N, const float* __restrict__ add)
{
    int c  = blockIdx.x * 64 + (threadIdx.x & 63);
    int ks = threadIdx.x >> 6;
    int kper = K >> 2;
    int k0 = ks * kper, k1 = k0 + kper;
    float s = 0.f;
    for (int k = k0; k < k1; k++) s = fmaf(x[k], W[(size_t)k * N + c], s);
    __shared__ float sm[4][64];
    sm[ks][threadIdx.x & 63] = s;
    __syncthreads();
    if (ks == 0) {
        int l = threadIdx.x & 63;
        float v = sm[0][l] + sm[1][l] + sm[2][l] + sm[3][l];
        if (add) v += add[c];
        y[c] = v;
    }
}

// ---------------- generic warp-per-output dot kernels ----------
__device__ __forceinline__ float warp_sum(float s) {
#pragma unroll
    for (int o = 16; o > 0; o >>= 1) s += __shfl_down_sync(0xffffffffu, s, o);
    return s;
}

__global__ __launch_bounds__(256)
void k_hdot(const float* __restrict__ W, const float* __restrict__ v,
            float* __restrict__ out) {
    int wg = blockIdx.x * 8 + (threadIdx.x >> 5);
    int lane = threadIdx.x & 31;
    int k = wg / 3, h = wg - k * 3;
    const float* row = W + (size_t)k * HD + h * N_OUT;
    const float* vv  = v + h * N_OUT;
    float s = 0.f;
#pragma unroll
    for (int j = lane; j < N_OUT; j += 32) s = fmaf(row[j], vv[j], s);
    s = warp_sum(s);
    if (lane == 0) out[k * 3 + h] = s;
}

__global__ __launch_bounds__(256)
void k_mat3(const float* __restrict__ M, const float* __restrict__ vec,
            float* __restrict__ out) {
    int wg = blockIdx.x * 8 + (threadIdx.x >> 5);
    int lane = threadIdx.x & 31;
    int k = wg / 3, h = wg - k * 3;
    const float* row = M + (size_t)k * N_INP;
    float s = 0.f;
#pragma unroll
    for (int c = lane; c < N_INP; c += 32) s = fmaf(row[c], vec[c * 3 + h], s);
    s = warp_sum(s);
    if (lane == 0) out[k * 3 + h] = s;
}

__global__ void k_b3(const float* __restrict__ b, const float* __restrict__ vec,
                     float* __restrict__ out3) {
    int w = threadIdx.x >> 5, lane = threadIdx.x & 31;
    if (w >= NH) return;
    float s = 0.f;
    for (int c = lane; c < N_INP; c += 32)
        s = fmaf(b[c], vec[c * 3 + w], s);
    s = warp_sum(s);
    if (lane == 0) out3[w] = s;
}

// ---------------- transpose + fp16 round ----
__global__ void k_w2t() {
    __shared__ float tile[32][33];
    int nb = blockIdx.x * 32, kb = blockIdx.y * 32;
    int tx = threadIdx.x, ty = threadIdx.y;
#pragma unroll
    for (int j = 0; j < 32; j += 8)
        tile[ty + j][tx] = d_W2[(size_t)(kb + ty + j) * N_OUT + nb + tx];
    __syncthreads();
#pragma unroll
    for (int j = 0; j < 32; j += 8)
        d_W2Th[(size_t)(nb + ty + j) * KAGG + kb + tx] = __float2half_rn(tile[tx][ty + j]);
}

// ---------------- FUSED: emb_api fp32 -> fp16 + api node logits ----------------
__global__ __launch_bounds__(256)
void k_embel(const float* __restrict__ emb,
             const float* __restrict__ V,
             const float* __restrict__ b3)
{
    __shared__ float sv0[N_INP], sv1[N_INP], sv2[N_INP];
    __shared__ float sb[NH];
    int t = threadIdx.x;
    for (int i = t; i < N_INP; i += 256) {
        sv0[i] = V[i * 3 + 0];
        sv1[i] = V[i * 3 + 1];
        sv2[i] = V[i * 3 + 2];
    }
    if (t < NH) sb[t] = b3[t];
    __syncthreads();

    int wid = t >> 5, lane = t & 31;
    int n = blockIdx.x * 8 + wid;
    const float2* x2 = (const float2*)(emb + (size_t)n * N_INP);
    __half2* o2 = (__half2*)(d_embh + (size_t)n * N_INP);

    float s0 = 0.f, s1 = 0.f, s2 = 0.f;
#pragma unroll
    for (int j = 0; j < 8; j++) {
        int idx = j * 32 + lane;
        float2 xv = x2[idx];
        o2[idx] = __floats2half2_rn(xv.x, xv.y);
        int k = idx * 2;
        float2 v0 = *(const float2*)&sv0[k];
        float2 v1 = *(const float2*)&sv1[k];
        float2 v2 = *(const float2*)&sv2[k];
        s0 = fmaf(xv.x, v0.x, fmaf(xv.y, v0.y, s0));
        s1 = fmaf(xv.x, v1.x, fmaf(xv.y, v1.y, s1));
        s2 = fmaf(xv.x, v2.x, fmaf(xv.y, v2.y, s2));
    }
    s0 = warp_sum(s0); s1 = warp_sum(s1); s2 = warp_sum(s2);
    if (lane == 0)
        *(float4*)(d_el + (size_t)n * 4) = make_float4(s0 + sb[0], s1 + sb[1], s2 + sb[2], 0.f);
}

// ---------------- node logits (file side) ----------------
__global__ void node_logits(const float* __restrict__ X,
                            const float* __restrict__ V,
                            const float* __restrict__ b3,
                            float* __restrict__ out, int Nn)
{
    __shared__ float sV[N_INP * NH];
    int t = threadIdx.x;
    for (int i = t; i < N_INP * NH; i += blockDim.x) sV[i] = V[i];
    __syncthreads();
    int warp = t >> 5, lane = t & 31;
    int n = blockIdx.x * (blockDim.x >> 5) + warp;
    if (n >= Nn) return;
    const float* x = X + (size_t)n * N_INP;
    float s0 = 0.f, s1 = 0.f, s2 = 0.f;
    for (int k = lane; k < N_INP; k += 32) {
        float xv = x[k];
        s0 = fmaf(xv, sV[k * 3 + 0], s0);
        s1 = fmaf(xv, sV[k * 3 + 1], s1);
        s2 = fmaf(xv, sV[k * 3 + 2], s2);
    }
#pragma unroll
    for (int o = 16; o > 0; o >>= 1) {
        s0 += __shfl_down_sync(0xffffffffu, s0, o);
        s1 += __shfl_down_sync(0xffffffffu, s1, o);
        s2 += __shfl_down_sync(0xffffffffu, s2, o);
    }
    if (lane == 0)
        *(float4*)(out + (size_t)n * 4) = make_float4(s0 + b3[0], s1 + b3[1], s2 + b3[2], 0.f);
}

// ---------------- CSR build (multi-block scan) ----------------
__global__ void k_zero() {
    int i = blockIdx.x * blockDim.x + threadIdx.x;
    if (i < N_FILE) { d_deg[i] = 0; d_cur[i] = 0; }
}

__global__ void k_count(const int* __restrict__ dst, int E) {
    int i = blockIdx.x * blockDim.x + threadIdx.x;
    if (i < E) atomicAdd(&d_deg[dst[i]], 1);
}

__global__ void k_scan1() {
    __shared__ int sh[512];
    int i = blockIdx.x * 512 + threadIdx.x;
    int v = (i < N_FILE) ? d_deg[i] : 0;
    sh[threadIdx.x] = v;
    __syncthreads();
    for (int o = 1; o < 512; o <<= 1) {
        int t = (threadIdx.x >= o) ? sh[threadIdx.x - o] : 0;
        __syncthreads();
        sh[threadIdx.x] += t;
        __syncthreads();
    }
    if (i < N_FILE) d_off[i] = sh[threadIdx.x] - v;
    if (threadIdx.x == 511) d_bsum[blockIdx.x] = sh[511];
}

__global__ void k_scan2() {
    if (threadIdx.x == 0) {
        int run = 0;
#pragma unroll
        for (int b = 0; b < SCAN_BLOCKS; b++) { d_bbase[b] = run; run += d_bsum[b]; }
        d_off[N_FILE] = run;
    }
}

__global__ void k_scan3() {
    int i = blockIdx.x * 512 + threadIdx.x;
    if (i < N_FILE) {
        d_off[i] += d_bbase[blockIdx.x];
        d_hasedge[i] = d_deg[i] ? 1.f : 0.f;
    }
}

__global__ void k_scatter(const int* __restrict__ src, const int* __restrict__ dst, int E) {
    int i = blockIdx.x * blockDim.x + threadIdx.x;
    if (i >= E) return;
    int d = dst[i];
    int p = atomicAdd(&d_cur[d], 1);
    d_srcs[d_off[d] + p] = src[i];
}

// ---------------- warp-per-dst single-pass softmax aggregation ----------------
// One warp per dst node. No shared memory, no block barriers.
// Accumulates unnormalized sum + z in one pass; scales by 1/z at the end.
// Logits are analytically bounded (|l| < ~10), so exp() can't overflow.
__global__ __launch_bounds__(256)
void gat_aggregate(int dbase)
{
    int w = threadIdx.x >> 5, lane = threadIdx.x & 31;
    int d = dbase + blockIdx.x * 8 + w;
    int start = d_off[d], end = d_off[d + 1];

    float4 er4 = *(const float4*)(d_er + (size_t)d * 4);
    float er0 = er4.x, er1 = er4.y, er2 = er4.z;
    const float4* el4 = (const float4*)d_el;

    // each lane owns 16 consecutive cols of the 512-col emb row
    const int c0 = lane * 16;
    float acc0[16], acc1[16], acc2[16];
#pragma unroll
    for (int i = 0; i < 16; i++) { acc0[i] = 0.f; acc1[i] = 0.f; acc2[i] = 0.f; }
    float zl0 = 0.f, zl1 = 0.f, zl2 = 0.f;

    for (int base = start; base < end; base += 32) {
        int e = base + lane;
        float w0 = 0.f, w1 = 0.f, w2 = 0.f;
        int s = 0;
        if (e < end) {
            s = d_srcs[e];
            float4 L = el4[s];
            w0 = __expf(lrelu(L.x + er0));
            w1 = __expf(lrelu(L.y + er1));
            w2 = __expf(lrelu(L.z + er2));
        }
        zl0 += w0; zl1 += w1; zl2 += w2;

        int cnt = end - base;
        if (cnt > 32) cnt = 32;
        for (int i = 0; i < cnt; i++) {
            float sw0 = __shfl_sync(0xffffffffu, w0, i);
            float sw1 = __shfl_sync(0xffffffffu, w1, i);
            float sw2 = __shfl_sync(0xffffffffu, w2, i);
            int   ss  = __shfl_sync(0xffffffffu, s,  i);
            const uint4* row = (const uint4*)(d_embh + (size_t)ss * N_INP + c0);
            uint4 v0 = row[0];
            uint4 v1 = row[1];
#pragma unroll
            for (int j = 0; j < 4; j++) {
                uint32_t p = ((const uint32_t*)&v0)[j];
                float2 f = __half22float2(*(__half2*)&p);
                acc0[j * 2 + 0] = fmaf(sw0, f.x, acc0[j * 2 + 0]);
                acc0[j * 2 + 1] = fmaf(sw0, f.y, acc0[j * 2 + 1]);
                acc1[j * 2 + 0] = fmaf(sw1, f.x, acc1[j * 2 + 0]);
                acc1[j * 2 + 1] = fmaf(sw1, f.y, acc1[j * 2 + 1]);
                acc2[j * 2 + 0] = fmaf(sw2, f.x, acc2[j * 2 + 0]);
                acc2[j * 2 + 1] = fmaf(sw2, f.y, acc2[j * 2 + 1]);
            }
#pragma unroll
            for (int j = 0; j < 4; j++) {
                uint32_t p = ((const uint32_t*)&v1)[j];
                float2 f = __half22float2(*(__half2*)&p);
                acc0[8 + j * 2 + 0] = fmaf(sw0, f.x, acc0[8 + j * 2 + 0]);
                acc0[8 + j * 2 + 1] = fmaf(sw0, f.y, acc0[8 + j * 2 + 1]);
                acc1[8 + j * 2 + 0] = fmaf(sw1, f.x, acc1[8 + j * 2 + 0]);
                acc1[8 + j * 2 + 1] = fmaf(sw1, f.y, acc1[8 + j * 2 + 1]);
                acc2[8 + j * 2 + 0] = fmaf(sw2, f.x, acc2[8 + j * 2 + 0]);
                acc2[8 + j * 2 + 1] = fmaf(sw2, f.y, acc2[8 + j * 2 + 1]);
            }
        }
    }

    // warp-reduce z (xor tree so every lane gets the result)
#pragma unroll
    for (int o = 16; o > 0; o >>= 1) {
        zl0 += __shfl_xor_sync(0xffffffffu, zl0, o);
        zl1 += __shfl_xor_sync(0xffffffffu, zl1, o);
        zl2 += __shfl_xor_sync(0xffffffffu, zl2, o);
    }
    float iz0 = (zl0 > 0.f) ? 1.f / zl0 : 0.f;
    float iz1 = (zl1 > 0.f) ? 1.f / zl1 : 0.f;
    float iz2 = (zl2 > 0.f) ? 1.f / zl2 : 0.f;

    // scale + pack + store (each head: 16 floats -> 8 half2 -> 2 uint4)
    __half* aout = d_aggh + (size_t)d * KAGG;
#define STORE_HEAD(accv, iz, off) do {                                         \
    uint4 o0, o1;                                                              \
    uint32_t* po0 = (uint32_t*)&o0;                                            \
    uint32_t* po1 = (uint32_t*)&o1;                                            \
    _Pragma("unroll")                                                          \
    for (int j = 0; j < 4; j++) {                                              \
        __half2 h = __floats2half2_rn((accv)[j * 2] * (iz), (accv)[j * 2 + 1] * (iz)); \
        po0[j] = *(uint32_t*)&h;                                               \
    }                                                                          \
    _Pragma("unroll")                                                          \
    for (int j = 0; j < 4; j++) {                                              \
        __half2 h = __floats2half2_rn((accv)[8 + j * 2] * (iz), (accv)[8 + j * 2 + 1] * (iz)); \
        po1[j] = *(uint32_t*)&h;                                               \
    }                                                                          \
    uint4* dst4 = (uint4*)(aout + (off) + c0);                                 \
    dst4[0] = o0; dst4[1] = o1;                                                \
} while (0)

    STORE_HEAD(acc0, iz0, 0 * N_INP);
    STORE_HEAD(acc1, iz1, 1 * N_INP);
    STORE_HEAD(acc2, iz2, 2 * N_INP);
}

// ---------------- launch ----------------
extern "C" void kernel_launch(void* const* d_in, const int* in_sizes, int n_in,
                              void* d_out, int out_size)
{
    const float* emb_api  = (const float*)d_in[0];
    const float* emb_file = (const float*)d_in[1];
    const int*   src      = (const int*)d_in[3];
    const int*   dst      = (const int*)d_in[4];
    const float* Wapi     = (const float*)d_in[5];
    const float* bapi     = (const float*)d_in[6];
    const float* Wfile    = (const float*)d_in[7];
    const float* bfile    = (const float*)d_in[8];
    const float* Wsrc     = (const float*)d_in[9];
    const float* Wdst     = (const float*)d_in[10];
    const float* attn_l   = (const float*)d_in[11];
    const float* attn_r   = (const float*)d_in[12];
    const float* gat_bias = (const float*)d_in[13];
    const float* Whead    = (const float*)d_in[14];
    const float* bhead    = (const float*)d_in[15];
    float* out = (float*)d_out;

    const int E = in_sizes[3];

    float *p_Wcomb, *p_W2, *p_u, *p_vli, *p_Vl, *p_Vr, *p_bl, *p_br, *p_bconst,
          *p_cbias, *p_er, *p_hasedge, *p_bsrc;
    __half *p_W2Th, *p_aggh;
    cudaGetSymbolAddress((void**)&p_Wcomb,   d_Wcomb);
    cudaGetSymbolAddress((void**)&p_W2,      d_W2);
    cudaGetSymbolAddress((void**)&p_W2Th,    d_W2Th);
    cudaGetSymbolAddress((void**)&p_aggh,    d_aggh);
    cudaGetSymbolAddress((void**)&p_u,       d_u);
    cudaGetSymbolAddress((void**)&p_vli,     d_vli);
    cudaGetSymbolAddress((void**)&p_Vl,      d_Vl);
    cudaGetSymbolAddress((void**)&p_Vr,      d_Vr);
    cudaGetSymbolAddress((void**)&p_bl,      d_bl);
    cudaGetSymbolAddress((void**)&p_br,      d_br);
    cudaGetSymbolAddress((void**)&p_bconst,  d_bconst);
    cudaGetSymbolAddress((void**)&p_cbias,   d_cbias);
    cudaGetSymbolAddress((void**)&p_er,      d_er);
    cudaGetSymbolAddress((void**)&p_hasedge, d_hasedge);
    cudaGetSymbolAddress((void**)&p_bsrc,    d_bsrc);

    cudaFuncSetAttribute(gemm_mma, cudaFuncAttributeMaxDynamicSharedMemorySize, GEMM_SMEM_BYTES);

    static cudaStream_t s1 = nullptr, s2 = nullptr, s3 = nullptr;
    static cudaEvent_t ev0, ev_csr, ev_s2, ev_a0, ev_a1, ev_done;
    if (!s1) {
        cudaStreamCreateWithFlags(&s1, cudaStreamNonBlocking);
        cudaStreamCreateWithFlags(&s2, cudaStreamNonBlocking);
        cudaStreamCreateWithFlags(&s3, cudaStreamNonBlocking);
        cudaEventCreateWithFlags(&ev0,     cudaEventDisableTiming);
        cudaEventCreateWithFlags(&ev_csr,  cudaEventDisableTiming);
        cudaEventCreateWithFlags(&ev_s2,   cudaEventDisableTiming);
        cudaEventCreateWithFlags(&ev_a0,   cudaEventDisableTiming);
        cudaEventCreateWithFlags(&ev_a1,   cudaEventDisableTiming);
        cudaEventCreateWithFlags(&ev_done, cudaEventDisableTiming);
    }

    // fork
    cudaEventRecord(ev0, 0);
    cudaStreamWaitEvent(s1, ev0, 0);
    cudaStreamWaitEvent(s2, ev0, 0);
    cudaStreamWaitEvent(s3, ev0, 0);

    // ---- s1: CSR build ----
    k_zero   <<<(N_FILE + 255) / 256, 256, 0, s1>>>();
    k_count  <<<(E + 255) / 256, 256, 0, s1>>>(dst, E);
    k_scan1  <<<SCAN_BLOCKS, 512, 0, s1>>>();
    k_scan2  <<<1, 32, 0, s1>>>();
    k_scan3  <<<SCAN_BLOCKS, 512, 0, s1>>>();
    k_scatter<<<(E + 255) / 256, 256, 0, s1>>>(src, dst, E);
    cudaEventRecord(ev_csr, s1);

    // ---- default: api logit path + fused fp16 conversion ----
    k_hdot<<<192, 256>>>(Wsrc, attn_l, p_vli);
    k_mat3<<<192, 256>>>(Wapi, p_vli, p_Vl);
    k_b3<<<1, 128>>>(bapi, p_vli, p_bl);
    k_embel<<<N_API / 8, 256>>>(emb_api, p_Vl, p_bl);

    // ---- s3: Wcomb -> W2 -> w2t ----
    sgemm<<<dim3(HD / BN, N_INP / BM, 1), 256, 0, s3>>>(
        Wapi, N_INP, Wsrc, HD, p_Wcomb, HD, N_INP, HD, N_INP, 0, 0, 0);
    sgemm<<<dim3(N_OUT / BN, N_INP / BM, NH), 256, 0, s3>>>(
        p_Wcomb, HD, Whead, N_OUT, p_W2, N_OUT,
        N_INP, N_OUT, N_OUT,
        (long)N_OUT, (long)N_OUT * N_OUT, (long)N_INP * N_OUT);
    k_w2t<<<dim3(N_OUT / 32, KAGG / 32), dim3(32, 8), 0, s3>>>();

    // ---- s2: file-side precompute + gemm epilogue constants ----
    k_hdot<<<192, 256, 0, s2>>>(Wdst, attn_r, p_u);
    k_mat3<<<192, 256, 0, s2>>>(Wfile, p_u, p_Vr);
    k_b3<<<1, 128, 0, s2>>>(bfile, p_u, p_br);
    node_logits<<<(N_FILE + 7) / 8, 256, 0, s2>>>(emb_file, p_Vr, p_br, p_er, N_FILE);
    gevm<<<HD / 64, 256, 0, s2>>>(bapi, Wsrc, p_bsrc, N_INP, HD, nullptr);
    gevm<<<N_OUT / 64, 256, 0, s2>>>(gat_bias, Whead, p_cbias, HD, N_OUT, bhead);
    gevm<<<N_OUT / 64, 256, 0, s2>>>(p_bsrc, Whead, p_bconst, HD, N_OUT, nullptr);
    cudaEventRecord(ev_s2, s2);

    // ---- default: aggregation chunks (warp-per-dst; 8 dsts per block) ----
    cudaStreamWaitEvent(0, ev_csr, 0);
    cudaStreamWaitEvent(0, ev_s2, 0);
    gat_aggregate<<<CH0_DST / 8, 256>>>(0);
    cudaEventRecord(ev_a0, 0);
    gat_aggregate<<<CH1_DST / 8, 256>>>(CH0_DST);
    cudaEventRecord(ev_a1, 0);

    // ---- s3: gemm chunks ----
    cudaStreamWaitEvent(s3, ev_csr, 0);
    cudaStreamWaitEvent(s3, ev_s2, 0);
    cudaStreamWaitEvent(s3, ev_a0, 0);
    gemm_mma<<<dim3(N_OUT / 128, CH0_BLOCKS), 256, GEMM_SMEM_BYTES, s3>>>(
        p_aggh, p_W2Th, out, p_cbias, p_bconst, p_hasedge, 0);
    cudaStreamWaitEvent(s3, ev_a1, 0);
    gemm_mma<<<dim3(N_OUT / 128, CH1_BLOCKS), 256, GEMM_SMEM_BYTES, s3>>>(
        p_aggh, p_W2Th, out, p_cbias, p_bconst, p_hasedge, CH0_BLOCKS);
    cudaEventRecord(ev_done, s3);

    // join
    cudaStreamWaitEvent(0, ev_done, 0);
}

// round 14
// speedup vs baseline: 1.0902x; 1.0902x over previous
#include <cuda_runtime.h>
#include <cuda_fp16.h>
#include <math_constants.h>
#include <cstdint>

// ---------------- problem constants ----------------
#define N_API   50000
#define N_FILE  20000
#define N_INP   512
#define N_OUT   256
#define NH      3
#define HD      768   // NH*N_OUT
#define KAGG    1536  // NH*N_INP
#define M_PAD   20096 // 157*128
#define NCHUNK  48    // KAGG/32 (k-chunk = 32 halfs)

// pipeline chunking: 157 row-blocks = 80 + 77
#define CH0_BLOCKS 80
#define CH1_BLOCKS 77
#define CH0_DST    (CH0_BLOCKS * 128)
#define CH1_DST    (N_FILE - CH0_DST)

#define SCAN_BLOCKS ((N_FILE + 511) / 512)   // 40

// ---------------- device scratch ----------------
__device__ float  d_Wcomb[N_INP * HD];
__device__ float  d_W2   [KAGG * N_OUT];
__device__ __half d_W2Th [N_OUT * KAGG];
__device__ __half d_embh [(size_t)N_API * N_INP];   // fp16 emb_api
__device__ __half d_aggh [(size_t)M_PAD * KAGG];    // fp16 agg (tail rows stay 0)
__device__ float  d_u    [N_INP * NH];
__device__ float  d_vli  [N_INP * NH];
__device__ float  d_Vl   [N_INP * NH];
__device__ float  d_Vr   [N_INP * NH];
__device__ float  d_bsrc [HD];
__device__ float  d_bl   [NH];
__device__ float  d_br   [NH];
__device__ float  d_bconst[N_OUT];
__device__ float  d_cbias [N_OUT];
__device__ float  d_el   [N_API * 4];
__device__ float  d_er   [N_FILE * 4];
__device__ int    d_deg  [N_FILE];
__device__ int    d_cur  [N_FILE];
__device__ int    d_off  [N_FILE + 1];
__device__ int    d_bsum [SCAN_BLOCKS];
__device__ int    d_bbase[SCAN_BLOCKS];
__device__ float  d_hasedge[N_FILE];
__device__ int    d_srcs [262144];

// ---------------- helpers ----------------
__device__ __forceinline__ uint32_t smem_u32(const void* p) {
    uint32_t a;
    asm("{ .reg .u64 t; cvta.to.shared.u64 t, %1; cvt.u32.u64 %0, t; }" : "=r"(a) : "l"(p));
    return a;
}
__device__ __forceinline__ float lrelu(float v) { return v > 0.f ? v : 0.2f * v; }

#define CP_ASYNC16(dst, src) \
    asm volatile("cp.async.cg.shared.global [%0], [%1], 16;" :: "r"(dst), "l"(src) : "memory")
#define CP_COMMIT()  asm volatile("cp.async.commit_group;" ::: "memory")
#define CP_WAIT0()   asm volatile("cp.async.wait_group 0;" ::: "memory")
#define CP_WAIT1()   asm volatile("cp.async.wait_group 1;" ::: "memory")

#define LDSM_X4(r0, r1, r2, r3, addr) \
    asm volatile("ldmatrix.sync.aligned.m8n8.x4.shared.b16 {%0,%1,%2,%3}, [%4];" \
                 : "=r"(r0), "=r"(r1), "=r"(r2), "=r"(r3) : "r"(addr))

__device__ __forceinline__ void mma_f16(float* c, const uint32_t* a, const uint32_t* b) {
    asm volatile(
        "mma.sync.aligned.m16n8k16.row.col.f32.f16.f16.f32 "
        "{%0,%1,%2,%3}, {%4,%5,%6,%7}, {%8,%9}, {%0,%1,%2,%3};"
        : "+f"(c[0]), "+f"(c[1]), "+f"(c[2]), "+f"(c[3])
        : "r"(a[0]), "r"(a[1]), "r"(a[2]), "r"(a[3]), "r"(b[0]), "r"(b[1]));
}

// ---------------- fp16 tensor-core GEMM with ldmatrix fragments ----------------
#define LDPH   40
#define TILEH  (128 * LDPH)
#define GEMM_SMEM_BYTES (4 * TILEH * 2)

__global__ void __launch_bounds__(256, 2)
gemm_mma(const __half* __restrict__ A, const __half* __restrict__ B,
         float* __restrict__ C,
         const float* __restrict__ cbias,
         const float* __restrict__ bconst,
         const float* __restrict__ hasedge,
         int mb_base)
{
    extern __shared__ __half smh[];
    __half* As = smh;
    __half* Bs = smh + 2 * TILEH;

    const int tid  = threadIdx.x;
    const int wid  = tid >> 5, lane = tid & 31;
    const int wm   = wid & 1;
    const int wn   = wid >> 1;
    const int m0   = (mb_base + blockIdx.y) * 128;
    const int n0   = blockIdx.x * 128;

    const uint32_t As_u = smem_u32(As);
    const uint32_t Bs_u = smem_u32(Bs);

    const uint32_t aOff = (uint32_t)(((wm * 64 + (lane & 15)) * LDPH + (lane >> 4) * 8) * 2);
    const uint32_t bOff = (uint32_t)(((wn * 32 + (lane & 7) + (lane >> 4) * 8) * LDPH
                                      + ((lane >> 3) & 1) * 8) * 2);

    float acc[4][4][4];
#pragma unroll
    for (int a = 0; a < 4; a++)
#pragma unroll
        for (int b = 0; b < 4; b++)
#pragma unroll
            for (int c = 0; c < 4; c++) acc[a][b][c] = 0.f;

#define LOAD_TILE(kt, s) do {                                                     \
    int _k0 = (kt) * 32;                                                          \
    _Pragma("unroll")                                                             \
    for (int _t = 0; _t < 2; _t++) {                                              \
        int _idx = tid + _t * 256;                                                \
        int _row = _idx >> 2, _seg = _idx & 3;                                    \
        const __half* _g = A + (size_t)(m0 + _row) * KAGG + _k0 + _seg * 8;       \
        CP_ASYNC16(As_u + (uint32_t)(((s) * TILEH + _row * LDPH + _seg * 8) * 2), _g); \
    }                                                                             \
    _Pragma("unroll")                                                             \
    for (int _t = 0; _t < 2; _t++) {                                              \
        int _idx = tid + _t * 256;                                                \
        int _row = _idx >> 2, _seg = _idx & 3;                                    \
        const __half* _g = B + (size_t)(n0 + _row) * KAGG + _k0 + _seg * 8;       \
        CP_ASYNC16(Bs_u + (uint32_t)(((s) * TILEH + _row * LDPH + _seg * 8) * 2), _g); \
    }                                                                             \
    CP_COMMIT();                                                                  \
} while (0)

    LOAD_TILE(0, 0);

    for (int kt = 0; kt < NCHUNK; kt++) {
        int s = kt & 1;
        if (kt + 1 < NCHUNK) { LOAD_TILE(kt + 1, s ^ 1); CP_WAIT1(); }
        else                 { CP_WAIT0(); }
        __syncthreads();

        const uint32_t aBase = As_u + (uint32_t)(s * TILEH * 2) + aOff;
        const uint32_t bBase = Bs_u + (uint32_t)(s * TILEH * 2) + bOff;

#pragma unroll
        for (int ks = 0; ks < 2; ks++) {
            const uint32_t kByte = (uint32_t)(ks * 32);
            uint32_t afr[4][4];
#pragma unroll
            for (int mi = 0; mi < 4; mi++)
                LDSM_X4(afr[mi][0], afr[mi][1], afr[mi][2], afr[mi][3],
                        aBase + (uint32_t)(mi * 16 * LDPH * 2) + kByte);
            uint32_t bfr[4][2];
#pragma unroll
            for (int nj = 0; nj < 2; nj++)
                LDSM_X4(bfr[nj * 2][0], bfr[nj * 2][1], bfr[nj * 2 + 1][0], bfr[nj * 2 + 1][1],
                        bBase + (uint32_t)(nj * 16 * LDPH * 2) + kByte);
#pragma unroll
            for (int mi = 0; mi < 4; mi++)
#pragma unroll
                for (int ni = 0; ni < 4; ni++)
                    mma_f16(acc[mi][ni], afr[mi], bfr[ni]);
        }
        __syncthreads();
    }

#pragma unroll
    for (int mi = 0; mi < 4; mi++) {
        int rbase = m0 + wm * 64 + mi * 16 + (lane >> 2);
#pragma unroll
        for (int half_ = 0; half_ < 2; half_++) {
            int r = rbase + half_ * 8;
            if (r >= N_FILE) continue;
            float he = hasedge[r];
#pragma unroll
            for (int ni = 0; ni < 4; ni++) {
                int c0 = n0 + wn * 32 + ni * 8 + (lane & 3) * 2;
                float v0 = acc[mi][ni][half_ * 2 + 0] + cbias[c0]     + he * bconst[c0];
                float v1 = acc[mi][ni][half_ * 2 + 1] + cbias[c0 + 1] + he * bconst[c0 + 1];
                *(float2*)(C + (size_t)r * N_OUT + c0) = make_float2(v0, v1);
            }
        }
    }
}

// ---------------- fp32 SGEMM (precompute-sized, batched z) ----
#define BM 128
#define BN 128
#define BK 8
#define TM 8
#define TN 8

__global__ __launch_bounds__(256, 2)
void sgemm(const float* __restrict__ A, int lda,
           const float* __restrict__ B, int ldb,
           float* __restrict__ C, int ldc,
           int M, int N, int K,
           long sA, long sB, long sC)
{
    A += (long)blockIdx.z * sA;
    B += (long)blockIdx.z * sB;
    C += (long)blockIdx.z * sC;

    __shared__ float As[BK][BM];
    __shared__ float Bs[BK][BN];
    const int tid = threadIdx.x;
    const int bm  = blockIdx.y * BM;
    const int bn  = blockIdx.x * BN;

    const int aRow  = tid >> 1;
    const int aCol4 = (tid & 1) * 4;
    const int bRow  = tid >> 5;
    const int bCol4 = (tid & 31) * 4;
    const int ty = tid >> 4, tx = tid & 15;

    float acc[TM][TN];
#pragma unroll
    for (int i = 0; i < TM; i++)
#pragma unroll
        for (int j = 0; j < TN; j++) acc[i][j] = 0.f;

    for (int k0 = 0; k0 < K; k0 += BK) {
        float4 av;
        if (bm + aRow < M)
            av = *(const float4*)(A + (size_t)(bm + aRow) * lda + k0 + aCol4);
        else
            av = make_float4(0.f, 0.f, 0.f, 0.f);
        As[aCol4 + 0][aRow] = av.x;
        As[aCol4 + 1][aRow] = av.y;
        As[aCol4 + 2][aRow] = av.z;
        As[aCol4 + 3][aRow] = av.w;

        float4 bv = *(const float4*)(B + (size_t)(k0 + bRow) * ldb + bn + bCol4);
        *(float4*)(&Bs[bRow][bCol4]) = bv;

        __syncthreads();
#pragma unroll
        for (int k = 0; k < BK; k++) {
            float ra[TM], rb[TN];
#pragma unroll
            for (int i = 0; i < TM; i++) ra[i] = As[k][ty * TM + i];
#pragma unroll
            for (int j = 0; j < TN; j++) rb[j] = Bs[k][tx * TN + j];
#pragma unroll
            for (int i = 0; i < TM; i++)
#pragma unroll
                for (int j = 0; j < TN; j++)
                    acc[i][j] = fmaf(ra[i], rb[j], acc[i][j]);
        }
        __syncthreads();
    }

#pragma unroll
    for (int i = 0; i < TM; i++) {
        int row = bm + ty * TM + i;
        if (row >= M) break;
#pragma unroll
        for (int j = 0; j < TN; j += 4) {
            int col = bn + tx * TN + j;
            float4 v;
            v.x = acc[i][j];     v.y = acc[i][j + 1];
            v.z = acc[i][j + 2]; v.w = acc[i][j + 3];
            *(float4*)(C + (size_t)row * ldc + col) = v;
        }
    }
}

// ---------------- coalesced GEVM ----------
__global__ __launch_bounds__(256)
void gevm(const float* __restrict__ x, const float* __restrict__ W,
          float* __restrict__ y, int K, int N, const float* __restrict__ add)
{
    int c  = blockIdx.x * 64 + (threadIdx.x & 63);
    int ks = threadIdx.x >> 6;
    int kper = K >> 2;
    int k0 = ks * kper, k1 = k0 + kper;
    float s = 0.f;
    for (int k = k0; k < k1; k++) s = fmaf(x[k], W[(size_t)k * N + c], s);
    __shared__ float sm[4][64];
    sm[ks][threadIdx.x & 63] = s;
    __syncthreads();
    if (ks == 0) {
        int l = threadIdx.x & 63;
        float v = sm[0][l] + sm[1][l] + sm[2][l] + sm[3][l];
        if (add) v += add[c];
        y[c] = v;
    }
}

// ---------------- generic warp-per-output dot kernels ----------
__device__ __forceinline__ float warp_sum(float s) {
#pragma unroll
    for (int o = 16; o > 0; o >>= 1) s += __shfl_down_sync(0xffffffffu, s, o);
    return s;
}

__global__ __launch_bounds__(256)
void k_hdot(const float* __restrict__ W, const float* __restrict__ v,
            float* __restrict__ out) {
    int wg = blockIdx.x * 8 + (threadIdx.x >> 5);
    int lane = threadIdx.x & 31;
    int k = wg / 3, h = wg - k * 3;
    const float* row = W + (size_t)k * HD + h * N_OUT;
    const float* vv  = v + h * N_OUT;
    float s = 0.f;
#pragma unroll
    for (int j = lane; j < N_OUT; j += 32) s = fmaf(row[j], vv[j], s);
    s = warp_sum(s);
    if (lane == 0) out[k * 3 + h] = s;
}

__global__ __launch_bounds__(256)
void k_mat3(const float* __restrict__ M, const float* __restrict__ vec,
            float* __restrict__ out) {
    int wg = blockIdx.x * 8 + (threadIdx.x >> 5);
    int lane = threadIdx.x & 31;
    int k = wg / 3, h = wg - k * 3;
    const float* row = M + (size_t)k * N_INP;
    float s = 0.f;
#pragma unroll
    for (int c = lane; c < N_INP; c += 32) s = fmaf(row[c], vec[c * 3 + h], s);
    s = warp_sum(s);
    if (lane == 0) out[k * 3 + h] = s;
}

__global__ void k_b3(const float* __restrict__ b, const float* __restrict__ vec,
                     float* __restrict__ out3) {
    int w = threadIdx.x >> 5, lane = threadIdx.x & 31;
    if (w >= NH) return;
    float s = 0.f;
    for (int c = lane; c < N_INP; c += 32)
        s = fmaf(b[c], vec[c * 3 + w], s);
    s = warp_sum(s);
    if (lane == 0) out3[w] = s;
}

// ---------------- transpose + fp16 round ----
__global__ void k_w2t() {
    __shared__ float tile[32][33];
    int nb = blockIdx.x * 32, kb = blockIdx.y * 32;
    int tx = threadIdx.x, ty = threadIdx.y;
#pragma unroll
    for (int j = 0; j < 32; j += 8)
        tile[ty + j][tx] = d_W2[(size_t)(kb + ty + j) * N_OUT + nb + tx];
    __syncthreads();
#pragma unroll
    for (int j = 0; j < 32; j += 8)
        d_W2Th[(size_t)(nb + ty + j) * KAGG + kb + tx] = __float2half_rn(tile[tx][ty + j]);
}

// ---------------- FUSED: emb_api fp32 -> fp16 + api node logits ----------------
__global__ __launch_bounds__(256)
void k_embel(const float* __restrict__ emb,
             const float* __restrict__ V,
             const float* __restrict__ b3)
{
    __shared__ float sv0[N_INP], sv1[N_INP], sv2[N_INP];
    __shared__ float sb[NH];
    int t = threadIdx.x;
    for (int i = t; i < N_INP; i += 256) {
        sv0[i] = V[i * 3 + 0];
        sv1[i] = V[i * 3 + 1];
        sv2[i] = V[i * 3 + 2];
    }
    if (t < NH) sb[t] = b3[t];
    __syncthreads();

    int wid = t >> 5, lane = t & 31;
    int n = blockIdx.x * 8 + wid;
    const float2* x2 = (const float2*)(emb + (size_t)n * N_INP);
    __half2* o2 = (__half2*)(d_embh + (size_t)n * N_INP);

    float s0 = 0.f, s1 = 0.f, s2 = 0.f;
#pragma unroll
    for (int j = 0; j < 8; j++) {
        int idx = j * 32 + lane;
        float2 xv = x2[idx];
        o2[idx] = __floats2half2_rn(xv.x, xv.y);
        int k = idx * 2;
        float2 v0 = *(const float2*)&sv0[k];
        float2 v1 = *(const float2*)&sv1[k];
        float2 v2 = *(const float2*)&sv2[k];
        s0 = fmaf(xv.x, v0.x, fmaf(xv.y, v0.y, s0));
        s1 = fmaf(xv.x, v1.x, fmaf(xv.y, v1.y, s1));
        s2 = fmaf(xv.x, v2.x, fmaf(xv.y, v2.y, s2));
    }
    s0 = warp_sum(s0); s1 = warp_sum(s1); s2 = warp_sum(s2);
    if (lane == 0)
        *(float4*)(d_el + (size_t)n * 4) = make_float4(s0 + sb[0], s1 + sb[1], s2 + sb[2], 0.f);
}

// ---------------- node logits (file side) ----------------
__global__ void node_logits(const float* __restrict__ X,
                            const float* __restrict__ V,
                            const float* __restrict__ b3,
                            float* __restrict__ out, int Nn)
{
    __shared__ float sV[N_INP * NH];
    int t = threadIdx.x;
    for (int i = t; i < N_INP * NH; i += blockDim.x) sV[i] = V[i];
    __syncthreads();
    int warp = t >> 5, lane = t & 31;
    int n = blockIdx.x * (blockDim.x >> 5) + warp;
    if (n >= Nn) return;
    const float* x = X + (size_t)n * N_INP;
    float s0 = 0.f, s1 = 0.f, s2 = 0.f;
    for (int k = lane; k < N_INP; k += 32) {
        float xv = x[k];
        s0 = fmaf(xv, sV[k * 3 + 0], s0);
        s1 = fmaf(xv, sV[k * 3 + 1], s1);
        s2 = fmaf(xv, sV[k * 3 + 2], s2);
    }
#pragma unroll
    for (int o = 16; o > 0; o >>= 1) {
        s0 += __shfl_down_sync(0xffffffffu, s0, o);
        s1 += __shfl_down_sync(0xffffffffu, s1, o);
        s2 += __shfl_down_sync(0xffffffffu, s2, o);
    }
    if (lane == 0)
        *(float4*)(out + (size_t)n * 4) = make_float4(s0 + b3[0], s1 + b3[1], s2 + b3[2], 0.f);
}

// ---------------- CSR build (multi-block scan) ----------------
__global__ void k_zero() {
    int i = blockIdx.x * blockDim.x + threadIdx.x;
    if (i < N_FILE) { d_deg[i] = 0; d_cur[i] = 0; }
}

__global__ void k_count(const int* __restrict__ dst, int E) {
    int i = blockIdx.x * blockDim.x + threadIdx.x;
    if (i < E) atomicAdd(&d_deg[dst[i]], 1);
}

__global__ void k_scan1() {
    __shared__ int sh[512];
    int i = blockIdx.x * 512 + threadIdx.x;
    int v = (i < N_FILE) ? d_deg[i] : 0;
    sh[threadIdx.x] = v;
    __syncthreads();
    for (int o = 1; o < 512; o <<= 1) {
        int t = (threadIdx.x >= o) ? sh[threadIdx.x - o] : 0;
        __syncthreads();
        sh[threadIdx.x] += t;
        __syncthreads();
    }
    if (i < N_FILE) d_off[i] = sh[threadIdx.x] - v;
    if (threadIdx.x == 511) d_bsum[blockIdx.x] = sh[511];
}

__global__ void k_scan2() {
    if (threadIdx.x == 0) {
        int run = 0;
#pragma unroll
        for (int b = 0; b < SCAN_BLOCKS; b++) { d_bbase[b] = run; run += d_bsum[b]; }
        d_off[N_FILE] = run;
    }
}

__global__ void k_scan3() {
    int i = blockIdx.x * 512 + threadIdx.x;
    if (i < N_FILE) {
        d_off[i] += d_bbase[blockIdx.x];
        d_hasedge[i] = d_deg[i] ? 1.f : 0.f;
    }
}

__global__ void k_scatter(const int* __restrict__ src, const int* __restrict__ dst, int E) {
    int i = blockIdx.x * blockDim.x + threadIdx.x;
    if (i >= E) return;
    int d = dst[i];
    int p = atomicAdd(&d_cur[d], 1);
    d_srcs[d_off[d] + p] = src[i];
}

// ---------------- per-dst softmax (no-max) + fp16 aggregation (round-12 proven) ----
#define GCAP 96

__global__ __launch_bounds__(128)
void gat_aggregate(int dbase)
{
    int d = dbase + blockIdx.x;
    int t = threadIdx.x;
    int lane = t & 31, warp = t >> 5;
    int start = d_off[d], end = d_off[d + 1];
    int deg = end - start;
    bool cached = (deg <= GCAP);

    __shared__ int   sh_src[GCAP];
    __shared__ float sh_w[GCAP * 3];
    __shared__ float s_er[4], s_iz[3];
    __shared__ float red[4][3];

    if (t < 4) s_er[t] = d_er[(size_t)d * 4 + t];
    __syncthreads();
    float er0 = s_er[0], er1 = s_er[1], er2 = s_er[2];
    const float4* el4 = (const float4*)d_el;

    // single pass: w = exp(lrelu(el+er)), cache, accumulate z
    float z0 = 0.f, z1 = 0.f, z2 = 0.f;
    for (int e = start + t; e < end; e += 128) {
        int s = d_srcs[e];
        float4 L = el4[s];
        float w0 = __expf(lrelu(L.x + er0));
        float w1 = __expf(lrelu(L.y + er1));
        float w2 = __expf(lrelu(L.z + er2));
        if (cached) {
            int i = e - start;
            sh_src[i] = s;
            sh_w[i * 3 + 0] = w0; sh_w[i * 3 + 1] = w1; sh_w[i * 3 + 2] = w2;
        }
        z0 += w0; z1 += w1; z2 += w2;
    }
#pragma unroll
    for (int o = 16; o > 0; o >>= 1) {
        z0 += __shfl_xor_sync(0xffffffffu, z0, o);
        z1 += __shfl_xor_sync(0xffffffffu, z1, o);
        z2 += __shfl_xor_sync(0xffffffffu, z2, o);
    }
    if (lane == 0) { red[warp][0] = z0; red[warp][1] = z1; red[warp][2] = z2; }
    __syncthreads();
    if (t < 3) {
        float z = red[0][t] + red[1][t] + red[2][t] + red[3][t];
        s_iz[t] = (z > 0.f) ? 1.f / z : 0.f;
    }
    __syncthreads();
    float iz0 = s_iz[0], iz1 = s_iz[1], iz2 = s_iz[2];

    if (cached) {
        for (int i = t; i < deg; i += 128) {
            sh_w[i * 3 + 0] *= iz0;
            sh_w[i * 3 + 1] *= iz1;
            sh_w[i * 3 + 2] *= iz2;
        }
    }
    __syncthreads();

    float a00 = 0.f, a01 = 0.f, a02 = 0.f, a03 = 0.f;
    float a10 = 0.f, a11 = 0.f, a12 = 0.f, a13 = 0.f;
    float a20 = 0.f, a21 = 0.f, a22 = 0.f, a23 = 0.f;
    int c4 = t * 4;

#define GATHER_FMA(sidx, w0, w1, w2) do {                                      \
    uint2 _v = *(const uint2*)(d_embh + (size_t)(sidx) * N_INP + c4);          \
    float2 _f0 = __half22float2(*(__half2*)&_v.x);                             \
    float2 _f1 = __half22float2(*(__half2*)&_v.y);                             \
    a00 = fmaf(w0, _f0.x, a00); a01 = fmaf(w0, _f0.y, a01);                    \
    a02 = fmaf(w0, _f1.x, a02); a03 = fmaf(w0, _f1.y, a03);                    \
    a10 = fmaf(w1, _f0.x, a10); a11 = fmaf(w1, _f0.y, a11);                    \
    a12 = fmaf(w1, _f1.x, a12); a13 = fmaf(w1, _f1.y, a13);                    \
    a20 = fmaf(w2, _f0.x, a20); a21 = fmaf(w2, _f0.y, a21);                    \
    a22 = fmaf(w2, _f1.x, a22); a23 = fmaf(w2, _f1.y, a23);                    \
} while (0)

    if (cached) {
        int i = 0;
        for (; i + 1 < deg; i += 2) {
            int   sA_ = sh_src[i],       sB_ = sh_src[i + 1];
            float wA0 = sh_w[i * 3 + 0], wB0 = sh_w[i * 3 + 3];
            float wA1 = sh_w[i * 3 + 1], wB1 = sh_w[i * 3 + 4];
            float wA2 = sh_w[i * 3 + 2], wB2 = sh_w[i * 3 + 5];
            GATHER_FMA(sA_, wA0, wA1, wA2);
            GATHER_FMA(sB_, wB0, wB1, wB2);
        }
        if (i < deg) {
            int s = sh_src[i];
            GATHER_FMA(s, sh_w[i * 3 + 0], sh_w[i * 3 + 1], sh_w[i * 3 + 2]);
        }
    } else {
        for (int e = start; e < end; e++) {
            int s = d_srcs[e];
            float4 L = el4[s];
            float w0 = __expf(lrelu(L.x + er0)) * iz0;
            float w1 = __expf(lrelu(L.y + er1)) * iz1;
            float w2 = __expf(lrelu(L.z + er2)) * iz2;
            GATHER_FMA(s, w0, w1, w2);
        }
    }

    __half* aout = d_aggh + (size_t)d * KAGG;
    __half2 o00 = __floats2half2_rn(a00, a01), o01 = __floats2half2_rn(a02, a03);
    __half2 o10 = __floats2half2_rn(a10, a11), o11 = __floats2half2_rn(a12, a13);
    __half2 o20 = __floats2half2_rn(a20, a21), o21 = __floats2half2_rn(a22, a23);
    uint2 w;
    w.x = *(uint32_t*)&o00; w.y = *(uint32_t*)&o01;
    *(uint2*)(aout + 0 * N_INP + c4) = w;
    w.x = *(uint32_t*)&o10; w.y = *(uint32_t*)&o11;
    *(uint2*)(aout + 1 * N_INP + c4) = w;
    w.x = *(uint32_t*)&o20; w.y = *(uint32_t*)&o21;
    *(uint2*)(aout + 2 * N_INP + c4) = w;
}

// ---------------- launch ----------------
extern "C" void kernel_launch(void* const* d_in, const int* in_sizes, int n_in,
                              void* d_out, int out_size)
{
    const float* emb_api  = (const float*)d_in[0];
    const float* emb_file = (const float*)d_in[1];
    const int*   src      = (const int*)d_in[3];
    const int*   dst      = (const int*)d_in[4];
    const float* Wapi     = (const float*)d_in[5];
    const float* bapi     = (const float*)d_in[6];
    const float* Wfile    = (const float*)d_in[7];
    const float* bfile    = (const float*)d_in[8];
    const float* Wsrc     = (const float*)d_in[9];
    const float* Wdst     = (const float*)d_in[10];
    const float* attn_l   = (const float*)d_in[11];
    const float* attn_r   = (const float*)d_in[12];
    const float* gat_bias = (const float*)d_in[13];
    const float* Whead    = (const float*)d_in[14];
    const float* bhead    = (const float*)d_in[15];
    float* out = (float*)d_out;

    const int E = in_sizes[3];

    float *p_Wcomb, *p_W2, *p_u, *p_vli, *p_Vl, *p_Vr, *p_bl, *p_br, *p_bconst,
          *p_cbias, *p_er, *p_hasedge, *p_bsrc;
    __half *p_W2Th, *p_aggh;
    cudaGetSymbolAddress((void**)&p_Wcomb,   d_Wcomb);
    cudaGetSymbolAddress((void**)&p_W2,      d_W2);
    cudaGetSymbolAddress((void**)&p_W2Th,    d_W2Th);
    cudaGetSymbolAddress((void**)&p_aggh,    d_aggh);
    cudaGetSymbolAddress((void**)&p_u,       d_u);
    cudaGetSymbolAddress((void**)&p_vli,     d_vli);
    cudaGetSymbolAddress((void**)&p_Vl,      d_Vl);
    cudaGetSymbolAddress((void**)&p_Vr,      d_Vr);
    cudaGetSymbolAddress((void**)&p_bl,      d_bl);
    cudaGetSymbolAddress((void**)&p_br,      d_br);
    cudaGetSymbolAddress((void**)&p_bconst,  d_bconst);
    cudaGetSymbolAddress((void**)&p_cbias,   d_cbias);
    cudaGetSymbolAddress((void**)&p_er,      d_er);
    cudaGetSymbolAddress((void**)&p_hasedge, d_hasedge);
    cudaGetSymbolAddress((void**)&p_bsrc,    d_bsrc);

    cudaFuncSetAttribute(gemm_mma, cudaFuncAttributeMaxDynamicSharedMemorySize, GEMM_SMEM_BYTES);

    static cudaStream_t s1 = nullptr, s2 = nullptr, s3 = nullptr;
    static cudaEvent_t ev0, ev_csr, ev_s2, ev_a0, ev_a1, ev_done;
    if (!s1) {
        cudaStreamCreateWithFlags(&s1, cudaStreamNonBlocking);
        cudaStreamCreateWithFlags(&s2, cudaStreamNonBlocking);
        cudaStreamCreateWithFlags(&s3, cudaStreamNonBlocking);
        cudaEventCreateWithFlags(&ev0,     cudaEventDisableTiming);
        cudaEventCreateWithFlags(&ev_csr,  cudaEventDisableTiming);
        cudaEventCreateWithFlags(&ev_s2,   cudaEventDisableTiming);
        cudaEventCreateWithFlags(&ev_a0,   cudaEventDisableTiming);
        cudaEventCreateWithFlags(&ev_a1,   cudaEventDisableTiming);
        cudaEventCreateWithFlags(&ev_done, cudaEventDisableTiming);
    }

    // fork
    cudaEventRecord(ev0, 0);
    cudaStreamWaitEvent(s1, ev0, 0);
    cudaStreamWaitEvent(s2, ev0, 0);
    cudaStreamWaitEvent(s3, ev0, 0);

    // ---- s1: CSR build + gemm epilogue constants (NOT agg-gating) ----
    k_zero   <<<(N_FILE + 255) / 256, 256, 0, s1>>>();
    k_count  <<<(E + 255) / 256, 256, 0, s1>>>(dst, E);
    k_scan1  <<<SCAN_BLOCKS, 512, 0, s1>>>();
    k_scan2  <<<1, 32, 0, s1>>>();
    k_scan3  <<<SCAN_BLOCKS, 512, 0, s1>>>();
    k_scatter<<<(E + 255) / 256, 256, 0, s1>>>(src, dst, E);
    gevm<<<HD / 64, 256, 0, s1>>>(bapi, Wsrc, p_bsrc, N_INP, HD, nullptr);
    gevm<<<N_OUT / 64, 256, 0, s1>>>(gat_bias, Whead, p_cbias, HD, N_OUT, bhead);
    gevm<<<N_OUT / 64, 256, 0, s1>>>(p_bsrc, Whead, p_bconst, HD, N_OUT, nullptr);
    cudaEventRecord(ev_csr, s1);

    // ---- default: api logit path + fused fp16 conversion ----
    k_hdot<<<192, 256>>>(Wsrc, attn_l, p_vli);
    k_mat3<<<192, 256>>>(Wapi, p_vli, p_Vl);
    k_b3<<<1, 128>>>(bapi, p_vli, p_bl);
    k_embel<<<N_API / 8, 256>>>(emb_api, p_Vl, p_bl);

    // ---- s3: Wcomb -> W2 -> w2t ----
    sgemm<<<dim3(HD / BN, N_INP / BM, 1), 256, 0, s3>>>(
        Wapi, N_INP, Wsrc, HD, p_Wcomb, HD, N_INP, HD, N_INP, 0, 0, 0);
    sgemm<<<dim3(N_OUT / BN, N_INP / BM, NH), 256, 0, s3>>>(
        p_Wcomb, HD, Whead, N_OUT, p_W2, N_OUT,
        N_INP, N_OUT, N_OUT,
        (long)N_OUT, (long)N_OUT * N_OUT, (long)N_INP * N_OUT);
    k_w2t<<<dim3(N_OUT / 32, KAGG / 32), dim3(32, 8), 0, s3>>>();

    // ---- s2: er path only (shorter agg gate) ----
    k_hdot<<<192, 256, 0, s2>>>(Wdst, attn_r, p_u);
    k_mat3<<<192, 256, 0, s2>>>(Wfile, p_u, p_Vr);
    k_b3<<<1, 128, 0, s2>>>(bfile, p_u, p_br);
    node_logits<<<(N_FILE + 7) / 8, 256, 0, s2>>>(emb_file, p_Vr, p_br, p_er, N_FILE);
    cudaEventRecord(ev_s2, s2);

    // ---- default: aggregation chunks (2-way, round-12 proven) ----
    cudaStreamWaitEvent(0, ev_csr, 0);
    cudaStreamWaitEvent(0, ev_s2, 0);
    gat_aggregate<<<CH0_DST, 128>>>(0);
    cudaEventRecord(ev_a0, 0);
    gat_aggregate<<<CH1_DST, 128>>>(CH0_DST);
    cudaEventRecord(ev_a1, 0);

    // ---- s3: gemm chunks ----
    cudaStreamWaitEvent(s3, ev_csr, 0);
    cudaStreamWaitEvent(s3, ev_s2, 0);
    cudaStreamWaitEvent(s3, ev_a0, 0);
    gemm_mma<<<dim3(N_OUT / 128, CH0_BLOCKS), 256, GEMM_SMEM_BYTES, s3>>>(
        p_aggh, p_W2Th, out, p_cbias, p_bconst, p_hasedge, 0);
    cudaStreamWaitEvent(s3, ev_a1, 0);
    gemm_mma<<<dim3(N_OUT / 128, CH1_BLOCKS), 256, GEMM_SMEM_BYTES, s3>>>(
        p_aggh, p_W2Th, out, p_cbias, p_bconst, p_hasedge, CH0_BLOCKS);
    cudaEventRecord(ev_done, s3);

    // join
    cudaStreamWaitEvent(0, ev_done, 0);
}

// round 15
// speedup vs baseline: 1.1263x; 1.0331x over previous
#include <cuda_runtime.h>
#include <cuda_fp16.h>
#include <math_constants.h>
#include <cstdint>

// ---------------- problem constants ----------------
#define N_API   50000
#define N_FILE  20000
#define N_INP   512
#define N_OUT   256
#define NH      3
#define HD      768   // NH*N_OUT
#define KAGG    1536  // NH*N_INP
#define M_PAD   20096 // 157*128
#define NCHUNK  48    // KAGG/32 (k-chunk = 32 halfs)

// pipeline chunking: 157 row-blocks = 106 + 51 (small exposed tail)
#define CH0_BLOCKS 106
#define CH1_BLOCKS 51
#define CH0_DST    (CH0_BLOCKS * 128)    // 13568
#define CH1_DST    (N_FILE - CH0_DST)    // 6432

#define SCAN_BLOCKS ((N_FILE + 511) / 512)   // 40

// ---------------- device scratch ----------------
__device__ float  d_Wcomb[N_INP * HD];
__device__ float  d_W2   [KAGG * N_OUT];
__device__ __half d_W2Th [N_OUT * KAGG];
__device__ __half d_embh [(size_t)N_API * N_INP];   // fp16 emb_api
__device__ __half d_aggh [(size_t)M_PAD * KAGG];    // fp16 agg (tail rows stay 0)
__device__ float  d_u    [N_INP * NH];
__device__ float  d_vli  [N_INP * NH];
__device__ float  d_Vl   [N_INP * NH];
__device__ float  d_Vr   [N_INP * NH];
__device__ float  d_bsrc [HD];
__device__ float  d_bl   [NH];
__device__ float  d_br   [NH];
__device__ float  d_bconst[N_OUT];
__device__ float  d_cbias [N_OUT];
__device__ float  d_el   [N_API * 4];
__device__ float  d_er   [N_FILE * 4];
__device__ int    d_deg  [N_FILE];
__device__ int    d_cur  [N_FILE];
__device__ int    d_off  [N_FILE + 1];
__device__ int    d_bsum [SCAN_BLOCKS];
__device__ int    d_bbase[SCAN_BLOCKS];
__device__ float  d_hasedge[N_FILE];
__device__ int    d_srcs [262144];

// ---------------- helpers ----------------
__device__ __forceinline__ uint32_t smem_u32(const void* p) {
    uint32_t a;
    asm("{ .reg .u64 t; cvta.to.shared.u64 t, %1; cvt.u32.u64 %0, t; }" : "=r"(a) : "l"(p));
    return a;
}
__device__ __forceinline__ float lrelu(float v) { return v > 0.f ? v : 0.2f * v; }

#define CP_ASYNC16(dst, src) \
    asm volatile("cp.async.cg.shared.global [%0], [%1], 16;" :: "r"(dst), "l"(src) : "memory")
#define CP_COMMIT()  asm volatile("cp.async.commit_group;" ::: "memory")
#define CP_WAIT0()   asm volatile("cp.async.wait_group 0;" ::: "memory")
#define CP_WAIT1()   asm volatile("cp.async.wait_group 1;" ::: "memory")

#define LDSM_X4(r0, r1, r2, r3, addr) \
    asm volatile("ldmatrix.sync.aligned.m8n8.x4.shared.b16 {%0,%1,%2,%3}, [%4];" \
                 : "=r"(r0), "=r"(r1), "=r"(r2), "=r"(r3) : "r"(addr))

__device__ __forceinline__ void mma_f16(float* c, const uint32_t* a, const uint32_t* b) {
    asm volatile(
        "mma.sync.aligned.m16n8k16.row.col.f32.f16.f16.f32 "
        "{%0,%1,%2,%3}, {%4,%5,%6,%7}, {%8,%9}, {%0,%1,%2,%3};"
        : "+f"(c[0]), "+f"(c[1]), "+f"(c[2]), "+f"(c[3])
        : "r"(a[0]), "r"(a[1]), "r"(a[2]), "r"(a[3]), "r"(b[0]), "r"(b[1]));
}

// ---------------- fp16 tensor-core GEMM with ldmatrix fragments ----------------
#define LDPH   40
#define TILEH  (128 * LDPH)
#define GEMM_SMEM_BYTES (4 * TILEH * 2)

__global__ void __launch_bounds__(256, 2)
gemm_mma(const __half* __restrict__ A, const __half* __restrict__ B,
         float* __restrict__ C,
         const float* __restrict__ cbias,
         const float* __restrict__ bconst,
         const float* __restrict__ hasedge,
         int mb_base)
{
    extern __shared__ __half smh[];
    __half* As = smh;
    __half* Bs = smh + 2 * TILEH;

    const int tid  = threadIdx.x;
    const int wid  = tid >> 5, lane = tid & 31;
    const int wm   = wid & 1;
    const int wn   = wid >> 1;
    const int m0   = (mb_base + blockIdx.y) * 128;
    const int n0   = blockIdx.x * 128;

    const uint32_t As_u = smem_u32(As);
    const uint32_t Bs_u = smem_u32(Bs);

    const uint32_t aOff = (uint32_t)(((wm * 64 + (lane & 15)) * LDPH + (lane >> 4) * 8) * 2);
    const uint32_t bOff = (uint32_t)(((wn * 32 + (lane & 7) + (lane >> 4) * 8) * LDPH
                                      + ((lane >> 3) & 1) * 8) * 2);

    float acc[4][4][4];
#pragma unroll
    for (int a = 0; a < 4; a++)
#pragma unroll
        for (int b = 0; b < 4; b++)
#pragma unroll
            for (int c = 0; c < 4; c++) acc[a][b][c] = 0.f;

#define LOAD_TILE(kt, s) do {                                                     \
    int _k0 = (kt) * 32;                                                          \
    _Pragma("unroll")                                                             \
    for (int _t = 0; _t < 2; _t++) {                                              \
        int _idx = tid + _t * 256;                                                \
        int _row = _idx >> 2, _seg = _idx & 3;                                    \
        const __half* _g = A + (size_t)(m0 + _row) * KAGG + _k0 + _seg * 8;       \
        CP_ASYNC16(As_u + (uint32_t)(((s) * TILEH + _row * LDPH + _seg * 8) * 2), _g); \
    }                                                                             \
    _Pragma("unroll")                                                             \
    for (int _t = 0; _t < 2; _t++) {                                              \
        int _idx = tid + _t * 256;                                                \
        int _row = _idx >> 2, _seg = _idx & 3;                                    \
        const __half* _g = B + (size_t)(n0 + _row) * KAGG + _k0 + _seg * 8;       \
        CP_ASYNC16(Bs_u + (uint32_t)(((s) * TILEH + _row * LDPH + _seg * 8) * 2), _g); \
    }                                                                             \
    CP_COMMIT();                                                                  \
} while (0)

    LOAD_TILE(0, 0);

    for (int kt = 0; kt < NCHUNK; kt++) {
        int s = kt & 1;
        if (kt + 1 < NCHUNK) { LOAD_TILE(kt + 1, s ^ 1); CP_WAIT1(); }
        else                 { CP_WAIT0(); }
        __syncthreads();

        const uint32_t aBase = As_u + (uint32_t)(s * TILEH * 2) + aOff;
        const uint32_t bBase = Bs_u + (uint32_t)(s * TILEH * 2) + bOff;

#pragma unroll
        for (int ks = 0; ks < 2; ks++) {
            const uint32_t kByte = (uint32_t)(ks * 32);
            uint32_t afr[4][4];
#pragma unroll
            for (int mi = 0; mi < 4; mi++)
                LDSM_X4(afr[mi][0], afr[mi][1], afr[mi][2], afr[mi][3],
                        aBase + (uint32_t)(mi * 16 * LDPH * 2) + kByte);
            uint32_t bfr[4][2];
#pragma unroll
            for (int nj = 0; nj < 2; nj++)
                LDSM_X4(bfr[nj * 2][0], bfr[nj * 2][1], bfr[nj * 2 + 1][0], bfr[nj * 2 + 1][1],
                        bBase + (uint32_t)(nj * 16 * LDPH * 2) + kByte);
#pragma unroll
            for (int mi = 0; mi < 4; mi++)
#pragma unroll
                for (int ni = 0; ni < 4; ni++)
                    mma_f16(acc[mi][ni], afr[mi], bfr[ni]);
        }
        __syncthreads();
    }

#pragma unroll
    for (int mi = 0; mi < 4; mi++) {
        int rbase = m0 + wm * 64 + mi * 16 + (lane >> 2);
#pragma unroll
        for (int half_ = 0; half_ < 2; half_++) {
            int r = rbase + half_ * 8;
            if (r >= N_FILE) continue;
            float he = hasedge[r];
#pragma unroll
            for (int ni = 0; ni < 4; ni++) {
                int c0 = n0 + wn * 32 + ni * 8 + (lane & 3) * 2;
                float v0 = acc[mi][ni][half_ * 2 + 0] + cbias[c0]     + he * bconst[c0];
                float v1 = acc[mi][ni][half_ * 2 + 1] + cbias[c0 + 1] + he * bconst[c0 + 1];
                *(float2*)(C + (size_t)r * N_OUT + c0) = make_float2(v0, v1);
            }
        }
    }
}

// ---------------- fp32 SGEMM (precompute-sized, batched z) ----
#define BM 128
#define BN 128
#define BK 8
#define TM 8
#define TN 8

__global__ __launch_bounds__(256, 2)
void sgemm(const float* __restrict__ A, int lda,
           const float* __restrict__ B, int ldb,
           float* __restrict__ C, int ldc,
           int M, int N, int K,
           long sA, long sB, long sC)
{
    A += (long)blockIdx.z * sA;
    B += (long)blockIdx.z * sB;
    C += (long)blockIdx.z * sC;

    __shared__ float As[BK][BM];
    __shared__ float Bs[BK][BN];
    const int tid = threadIdx.x;
    const int bm  = blockIdx.y * BM;
    const int bn  = blockIdx.x * BN;

    const int aRow  = tid >> 1;
    const int aCol4 = (tid & 1) * 4;
    const int bRow  = tid >> 5;
    const int bCol4 = (tid & 31) * 4;
    const int ty = tid >> 4, tx = tid & 15;

    float acc[TM][TN];
#pragma unroll
    for (int i = 0; i < TM; i++)
#pragma unroll
        for (int j = 0; j < TN; j++) acc[i][j] = 0.f;

    for (int k0 = 0; k0 < K; k0 += BK) {
        float4 av;
        if (bm + aRow < M)
            av = *(const float4*)(A + (size_t)(bm + aRow) * lda + k0 + aCol4);
        else
            av = make_float4(0.f, 0.f, 0.f, 0.f);
        As[aCol4 + 0][aRow] = av.x;
        As[aCol4 + 1][aRow] = av.y;
        As[aCol4 + 2][aRow] = av.z;
        As[aCol4 + 3][aRow] = av.w;

        float4 bv = *(const float4*)(B + (size_t)(k0 + bRow) * ldb + bn + bCol4);
        *(float4*)(&Bs[bRow][bCol4]) = bv;

        __syncthreads();
#pragma unroll
        for (int k = 0; k < BK; k++) {
            float ra[TM], rb[TN];
#pragma unroll
            for (int i = 0; i < TM; i++) ra[i] = As[k][ty * TM + i];
#pragma unroll
            for (int j = 0; j < TN; j++) rb[j] = Bs[k][tx * TN + j];
#pragma unroll
            for (int i = 0; i < TM; i++)
#pragma unroll
                for (int j = 0; j < TN; j++)
                    acc[i][j] = fmaf(ra[i], rb[j], acc[i][j]);
        }
        __syncthreads();
    }

#pragma unroll
    for (int i = 0; i < TM; i++) {
        int row = bm + ty * TM + i;
        if (row >= M) break;
#pragma unroll
        for (int j = 0; j < TN; j += 4) {
            int col = bn + tx * TN + j;
            float4 v;
            v.x = acc[i][j];     v.y = acc[i][j + 1];
            v.z = acc[i][j + 2]; v.w = acc[i][j + 3];
            *(float4*)(C + (size_t)row * ldc + col) = v;
        }
    }
}

// ---------------- coalesced GEVM ----------
__global__ __launch_bounds__(256)
void gevm(const float* __restrict__ x, const float* __restrict__ W,
          float* __restrict__ y, int K, int N, const float* __restrict__ add)
{
    int c  = blockIdx.x * 64 + (threadIdx.x & 63);
    int ks = threadIdx.x >> 6;
    int kper = K >> 2;
    int k0 = ks * kper, k1 = k0 + kper;
    float s = 0.f;
    for (int k = k0; k < k1; k++) s = fmaf(x[k], W[(size_t)k * N + c], s);
    __shared__ float sm[4][64];
    sm[ks][threadIdx.x & 63] = s;
    __syncthreads();
    if (ks == 0) {
        int l = threadIdx.x & 63;
        float v = sm[0][l] + sm[1][l] + sm[2][l] + sm[3][l];
        if (add) v += add[c];
        y[c] = v;
    }
}

// ---------------- generic warp-per-output dot kernels ----------
__device__ __forceinline__ float warp_sum(float s) {
#pragma unroll
    for (int o = 16; o > 0; o >>= 1) s += __shfl_down_sync(0xffffffffu, s, o);
    return s;
}

__global__ __launch_bounds__(256)
void k_hdot(const float* __restrict__ W, const float* __restrict__ v,
            float* __restrict__ out) {
    int wg = blockIdx.x * 8 + (threadIdx.x >> 5);
    int lane = threadIdx.x & 31;
    int k = wg / 3, h = wg - k * 3;
    const float* row = W + (size_t)k * HD + h * N_OUT;
    const float* vv  = v + h * N_OUT;
    float s = 0.f;
#pragma unroll
    for (int j = lane; j < N_OUT; j += 32) s = fmaf(row[j], vv[j], s);
    s = warp_sum(s);
    if (lane == 0) out[k * 3 + h] = s;
}

__global__ __launch_bounds__(256)
void k_mat3(const float* __restrict__ M, const float* __restrict__ vec,
            float* __restrict__ out) {
    int wg = blockIdx.x * 8 + (threadIdx.x >> 5);
    int lane = threadIdx.x & 31;
    int k = wg / 3, h = wg - k * 3;
    const float* row = M + (size_t)k * N_INP;
    float s = 0.f;
#pragma unroll
    for (int c = lane; c < N_INP; c += 32) s = fmaf(row[c], vec[c * 3 + h], s);
    s = warp_sum(s);
    if (lane == 0) out[k * 3 + h] = s;
}

__global__ void k_b3(const float* __restrict__ b, const float* __restrict__ vec,
                     float* __restrict__ out3) {
    int w = threadIdx.x >> 5, lane = threadIdx.x & 31;
    if (w >= NH) return;
    float s = 0.f;
    for (int c = lane; c < N_INP; c += 32)
        s = fmaf(b[c], vec[c * 3 + w], s);
    s = warp_sum(s);
    if (lane == 0) out3[w] = s;
}

// ---------------- transpose + fp16 round ----
__global__ void k_w2t() {
    __shared__ float tile[32][33];
    int nb = blockIdx.x * 32, kb = blockIdx.y * 32;
    int tx = threadIdx.x, ty = threadIdx.y;
#pragma unroll
    for (int j = 0; j < 32; j += 8)
        tile[ty + j][tx] = d_W2[(size_t)(kb + ty + j) * N_OUT + nb + tx];
    __syncthreads();
#pragma unroll
    for (int j = 0; j < 32; j += 8)
        d_W2Th[(size_t)(nb + ty + j) * KAGG + kb + tx] = __float2half_rn(tile[tx][ty + j]);
}

// ---------------- FUSED: emb_api fp32 -> fp16 + api node logits ----------------
__global__ __launch_bounds__(256)
void k_embel(const float* __restrict__ emb,
             const float* __restrict__ V,
             const float* __restrict__ b3)
{
    __shared__ float sv0[N_INP], sv1[N_INP], sv2[N_INP];
    __shared__ float sb[NH];
    int t = threadIdx.x;
    for (int i = t; i < N_INP; i += 256) {
        sv0[i] = V[i * 3 + 0];
        sv1[i] = V[i * 3 + 1];
        sv2[i] = V[i * 3 + 2];
    }
    if (t < NH) sb[t] = b3[t];
    __syncthreads();

    int wid = t >> 5, lane = t & 31;
    int n = blockIdx.x * 8 + wid;
    const float2* x2 = (const float2*)(emb + (size_t)n * N_INP);
    __half2* o2 = (__half2*)(d_embh + (size_t)n * N_INP);

    float s0 = 0.f, s1 = 0.f, s2 = 0.f;
#pragma unroll
    for (int j = 0; j < 8; j++) {
        int idx = j * 32 + lane;
        float2 xv = x2[idx];
        o2[idx] = __floats2half2_rn(xv.x, xv.y);
        int k = idx * 2;
        float2 v0 = *(const float2*)&sv0[k];
        float2 v1 = *(const float2*)&sv1[k];
        float2 v2 = *(const float2*)&sv2[k];
        s0 = fmaf(xv.x, v0.x, fmaf(xv.y, v0.y, s0));
        s1 = fmaf(xv.x, v1.x, fmaf(xv.y, v1.y, s1));
        s2 = fmaf(xv.x, v2.x, fmaf(xv.y, v2.y, s2));
    }
    s0 = warp_sum(s0); s1 = warp_sum(s1); s2 = warp_sum(s2);
    if (lane == 0)
        *(float4*)(d_el + (size_t)n * 4) = make_float4(s0 + sb[0], s1 + sb[1], s2 + sb[2], 0.f);
}

// ---------------- node logits (file side) ----------------
__global__ void node_logits(const float* __restrict__ X,
                            const float* __restrict__ V,
                            const float* __restrict__ b3,
                            float* __restrict__ out, int Nn)
{
    __shared__ float sV[N_INP * NH];
    int t = threadIdx.x;
    for (int i = t; i < N_INP * NH; i += blockDim.x) sV[i] = V[i];
    __syncthreads();
    int warp = t >> 5, lane = t & 31;
    int n = blockIdx.x * (blockDim.x >> 5) + warp;
    if (n >= Nn) return;
    const float* x = X + (size_t)n * N_INP;
    float s0 = 0.f, s1 = 0.f, s2 = 0.f;
    for (int k = lane; k < N_INP; k += 32) {
        float xv = x[k];
        s0 = fmaf(xv, sV[k * 3 + 0], s0);
        s1 = fmaf(xv, sV[k * 3 + 1], s1);
        s2 = fmaf(xv, sV[k * 3 + 2], s2);
    }
#pragma unroll
    for (int o = 16; o > 0; o >>= 1) {
        s0 += __shfl_down_sync(0xffffffffu, s0, o);
        s1 += __shfl_down_sync(0xffffffffu, s1, o);
        s2 += __shfl_down_sync(0xffffffffu, s2, o);
    }
    if (lane == 0)
        *(float4*)(out + (size_t)n * 4) = make_float4(s0 + b3[0], s1 + b3[1], s2 + b3[2], 0.f);
}

// ---------------- CSR build (multi-block scan) ----------------
__global__ void k_zero() {
    int i = blockIdx.x * blockDim.x + threadIdx.x;
    if (i < N_FILE) { d_deg[i] = 0; d_cur[i] = 0; }
}

__global__ void k_count(const int* __restrict__ dst, int E) {
    int i = blockIdx.x * blockDim.x + threadIdx.x;
    if (i < E) atomicAdd(&d_deg[dst[i]], 1);
}

__global__ void k_scan1() {
    __shared__ int sh[512];
    int i = blockIdx.x * 512 + threadIdx.x;
    int v = (i < N_FILE) ? d_deg[i] : 0;
    sh[threadIdx.x] = v;
    __syncthreads();
    for (int o = 1; o < 512; o <<= 1) {
        int t = (threadIdx.x >= o) ? sh[threadIdx.x - o] : 0;
        __syncthreads();
        sh[threadIdx.x] += t;
        __syncthreads();
    }
    if (i < N_FILE) d_off[i] = sh[threadIdx.x] - v;
    if (threadIdx.x == 511) d_bsum[blockIdx.x] = sh[511];
}

__global__ void k_scan2() {
    if (threadIdx.x == 0) {
        int run = 0;
#pragma unroll
        for (int b = 0; b < SCAN_BLOCKS; b++) { d_bbase[b] = run; run += d_bsum[b]; }
        d_off[N_FILE] = run;
    }
}

__global__ void k_scan3() {
    int i = blockIdx.x * 512 + threadIdx.x;
    if (i < N_FILE) {
        d_off[i] += d_bbase[blockIdx.x];
        d_hasedge[i] = d_deg[i] ? 1.f : 0.f;
    }
}

__global__ void k_scatter(const int* __restrict__ src, const int* __restrict__ dst, int E) {
    int i = blockIdx.x * blockDim.x + threadIdx.x;
    if (i >= E) return;
    int d = dst[i];
    int p = atomicAdd(&d_cur[d], 1);
    d_srcs[d_off[d] + p] = src[i];
}

// ---------------- per-dst softmax (no-max) + fp16 aggregation ----------------
#define GCAP 96

__global__ __launch_bounds__(128)
void gat_aggregate(int dbase)
{
    int d = dbase + blockIdx.x;
    int t = threadIdx.x;
    int lane = t & 31, warp = t >> 5;
    int start = d_off[d], end = d_off[d + 1];
    int deg = end - start;
    bool cached = (deg <= GCAP);

    __shared__ int   sh_src[GCAP];
    __shared__ float sh_w[GCAP * 3];
    __shared__ float s_er[4], s_iz[3];
    __shared__ float red[4][3];

    if (t < 4) s_er[t] = d_er[(size_t)d * 4 + t];
    __syncthreads();
    float er0 = s_er[0], er1 = s_er[1], er2 = s_er[2];
    const float4* el4 = (const float4*)d_el;

    // single pass: w = exp(lrelu(el+er)), cache, accumulate z
    float z0 = 0.f, z1 = 0.f, z2 = 0.f;
    for (int e = start + t; e < end; e += 128) {
        int s = d_srcs[e];
        float4 L = el4[s];
        float w0 = __expf(lrelu(L.x + er0));
        float w1 = __expf(lrelu(L.y + er1));
        float w2 = __expf(lrelu(L.z + er2));
        if (cached) {
            int i = e - start;
            sh_src[i] = s;
            sh_w[i * 3 + 0] = w0; sh_w[i * 3 + 1] = w1; sh_w[i * 3 + 2] = w2;
        }
        z0 += w0; z1 += w1; z2 += w2;
    }
#pragma unroll
    for (int o = 16; o > 0; o >>= 1) {
        z0 += __shfl_xor_sync(0xffffffffu, z0, o);
        z1 += __shfl_xor_sync(0xffffffffu, z1, o);
        z2 += __shfl_xor_sync(0xffffffffu, z2, o);
    }
    if (lane == 0) { red[warp][0] = z0; red[warp][1] = z1; red[warp][2] = z2; }
    __syncthreads();
    if (t < 3) {
        float z = red[0][t] + red[1][t] + red[2][t] + red[3][t];
        s_iz[t] = (z > 0.f) ? 1.f / z : 0.f;
    }
    __syncthreads();
    float iz0 = s_iz[0], iz1 = s_iz[1], iz2 = s_iz[2];

    if (cached) {
        for (int i = t; i < deg; i += 128) {
            sh_w[i * 3 + 0] *= iz0;
            sh_w[i * 3 + 1] *= iz1;
            sh_w[i * 3 + 2] *= iz2;
        }
    }
    __syncthreads();

    float a00 = 0.f, a01 = 0.f, a02 = 0.f, a03 = 0.f;
    float a10 = 0.f, a11 = 0.f, a12 = 0.f, a13 = 0.f;
    float a20 = 0.f, a21 = 0.f, a22 = 0.f, a23 = 0.f;
    int c4 = t * 4;

#define GATHER_FMA(sidx, w0, w1, w2) do {                                      \
    uint2 _v = *(const uint2*)(d_embh + (size_t)(sidx) * N_INP + c4);          \
    float2 _f0 = __half22float2(*(__half2*)&_v.x);                             \
    float2 _f1 = __half22float2(*(__half2*)&_v.y);                             \
    a00 = fmaf(w0, _f0.x, a00); a01 = fmaf(w0, _f0.y, a01);                    \
    a02 = fmaf(w0, _f1.x, a02); a03 = fmaf(w0, _f1.y, a03);                    \
    a10 = fmaf(w1, _f0.x, a10); a11 = fmaf(w1, _f0.y, a11);                    \
    a12 = fmaf(w1, _f1.x, a12); a13 = fmaf(w1, _f1.y, a13);                    \
    a20 = fmaf(w2, _f0.x, a20); a21 = fmaf(w2, _f0.y, a21);                    \
    a22 = fmaf(w2, _f1.x, a22); a23 = fmaf(w2, _f1.y, a23);                    \
} while (0)

    if (cached) {
        int i = 0;
        for (; i + 3 < deg; i += 4) {                 // x4 unroll (isolated test)
            int   sA_ = sh_src[i],       sB_ = sh_src[i + 1];
            int   sC_ = sh_src[i + 2],   sD_ = sh_src[i + 3];
            uint2 vA = *(const uint2*)(d_embh + (size_t)sA_ * N_INP + c4);
            uint2 vB = *(const uint2*)(d_embh + (size_t)sB_ * N_INP + c4);
            uint2 vC = *(const uint2*)(d_embh + (size_t)sC_ * N_INP + c4);
            uint2 vD = *(const uint2*)(d_embh + (size_t)sD_ * N_INP + c4);
#define APPLY(vv, base) do {                                                    \
            float2 _f0 = __half22float2(*(__half2*)&(vv).x);                    \
            float2 _f1 = __half22float2(*(__half2*)&(vv).y);                    \
            float w0 = sh_w[(base) * 3 + 0], w1 = sh_w[(base) * 3 + 1],         \
                  w2 = sh_w[(base) * 3 + 2];                                    \
            a00 = fmaf(w0, _f0.x, a00); a01 = fmaf(w0, _f0.y, a01);             \
            a02 = fmaf(w0, _f1.x, a02); a03 = fmaf(w0, _f1.y, a03);             \
            a10 = fmaf(w1, _f0.x, a10); a11 = fmaf(w1, _f0.y, a11);             \
            a12 = fmaf(w1, _f1.x, a12); a13 = fmaf(w1, _f1.y, a13);             \
            a20 = fmaf(w2, _f0.x, a20); a21 = fmaf(w2, _f0.y, a21);             \
            a22 = fmaf(w2, _f1.x, a22); a23 = fmaf(w2, _f1.y, a23);             \
        } while (0)
            APPLY(vA, i); APPLY(vB, i + 1); APPLY(vC, i + 2); APPLY(vD, i + 3);
        }
        for (; i < deg; i++) {
            int s = sh_src[i];
            GATHER_FMA(s, sh_w[i * 3 + 0], sh_w[i * 3 + 1], sh_w[i * 3 + 2]);
        }
    } else {
        for (int e = start; e < end; e++) {
            int s = d_srcs[e];
            float4 L = el4[s];
            float w0 = __expf(lrelu(L.x + er0)) * iz0;
            float w1 = __expf(lrelu(L.y + er1)) * iz1;
            float w2 = __expf(lrelu(L.z + er2)) * iz2;
            GATHER_FMA(s, w0, w1, w2);
        }
    }

    __half* aout = d_aggh + (size_t)d * KAGG;
    __half2 o00 = __floats2half2_rn(a00, a01), o01 = __floats2half2_rn(a02, a03);
    __half2 o10 = __floats2half2_rn(a10, a11), o11 = __floats2half2_rn(a12, a13);
    __half2 o20 = __floats2half2_rn(a20, a21), o21 = __floats2half2_rn(a22, a23);
    uint2 w;
    w.x = *(uint32_t*)&o00; w.y = *(uint32_t*)&o01;
    *(uint2*)(aout + 0 * N_INP + c4) = w;
    w.x = *(uint32_t*)&o10; w.y = *(uint32_t*)&o11;
    *(uint2*)(aout + 1 * N_INP + c4) = w;
    w.x = *(uint32_t*)&o20; w.y = *(uint32_t*)&o21;
    *(uint2*)(aout + 2 * N_INP + c4) = w;
}

// ---------------- launch ----------------
extern "C" void kernel_launch(void* const* d_in, const int* in_sizes, int n_in,
                              void* d_out, int out_size)
{
    const float* emb_api  = (const float*)d_in[0];
    const float* emb_file = (const float*)d_in[1];
    const int*   src      = (const int*)d_in[3];
    const int*   dst      = (const int*)d_in[4];
    const float* Wapi     = (const float*)d_in[5];
    const float* bapi     = (const float*)d_in[6];
    const float* Wfile    = (const float*)d_in[7];
    const float* bfile    = (const float*)d_in[8];
    const float* Wsrc     = (const float*)d_in[9];
    const float* Wdst     = (const float*)d_in[10];
    const float* attn_l   = (const float*)d_in[11];
    const float* attn_r   = (const float*)d_in[12];
    const float* gat_bias = (const float*)d_in[13];
    const float* Whead    = (const float*)d_in[14];
    const float* bhead    = (const float*)d_in[15];
    float* out = (float*)d_out;

    const int E = in_sizes[3];

    float *p_Wcomb, *p_W2, *p_u, *p_vli, *p_Vl, *p_Vr, *p_bl, *p_br, *p_bconst,
          *p_cbias, *p_er, *p_hasedge, *p_bsrc;
    __half *p_W2Th, *p_aggh;
    cudaGetSymbolAddress((void**)&p_Wcomb,   d_Wcomb);
    cudaGetSymbolAddress((void**)&p_W2,      d_W2);
    cudaGetSymbolAddress((void**)&p_W2Th,    d_W2Th);
    cudaGetSymbolAddress((void**)&p_aggh,    d_aggh);
    cudaGetSymbolAddress((void**)&p_u,       d_u);
    cudaGetSymbolAddress((void**)&p_vli,     d_vli);
    cudaGetSymbolAddress((void**)&p_Vl,      d_Vl);
    cudaGetSymbolAddress((void**)&p_Vr,      d_Vr);
    cudaGetSymbolAddress((void**)&p_bl,      d_bl);
    cudaGetSymbolAddress((void**)&p_br,      d_br);
    cudaGetSymbolAddress((void**)&p_bconst,  d_bconst);
    cudaGetSymbolAddress((void**)&p_cbias,   d_cbias);
    cudaGetSymbolAddress((void**)&p_er,      d_er);
    cudaGetSymbolAddress((void**)&p_hasedge, d_hasedge);
    cudaGetSymbolAddress((void**)&p_bsrc,    d_bsrc);

    cudaFuncSetAttribute(gemm_mma, cudaFuncAttributeMaxDynamicSharedMemorySize, GEMM_SMEM_BYTES);

    static cudaStream_t s1 = nullptr, s2 = nullptr, s3 = nullptr;
    static cudaEvent_t ev0, ev_csr, ev_s2, ev_a0, ev_a1, ev_done;
    if (!s1) {
        cudaStreamCreateWithFlags(&s1, cudaStreamNonBlocking);
        cudaStreamCreateWithFlags(&s2, cudaStreamNonBlocking);
        cudaStreamCreateWithFlags(&s3, cudaStreamNonBlocking);
        cudaEventCreateWithFlags(&ev0,     cudaEventDisableTiming);
        cudaEventCreateWithFlags(&ev_csr,  cudaEventDisableTiming);
        cudaEventCreateWithFlags(&ev_s2,   cudaEventDisableTiming);
        cudaEventCreateWithFlags(&ev_a0,   cudaEventDisableTiming);
        cudaEventCreateWithFlags(&ev_a1,   cudaEventDisableTiming);
        cudaEventCreateWithFlags(&ev_done, cudaEventDisableTiming);
    }

    // fork
    cudaEventRecord(ev0, 0);
    cudaStreamWaitEvent(s1, ev0, 0);
    cudaStreamWaitEvent(s2, ev0, 0);
    cudaStreamWaitEvent(s3, ev0, 0);

    // ---- s1: CSR build + gemm epilogue constants (NOT agg-gating) ----
    k_zero   <<<(N_FILE + 255) / 256, 256, 0, s1>>>();
    k_count  <<<(E + 255) / 256, 256, 0, s1>>>(dst, E);
    k_scan1  <<<SCAN_BLOCKS, 512, 0, s1>>>();
    k_scan2  <<<1, 32, 0, s1>>>();
    k_scan3  <<<SCAN_BLOCKS, 512, 0, s1>>>();
    k_scatter<<<(E + 255) / 256, 256, 0, s1>>>(src, dst, E);
    gevm<<<HD / 64, 256, 0, s1>>>(bapi, Wsrc, p_bsrc, N_INP, HD, nullptr);
    gevm<<<N_OUT / 64, 256, 0, s1>>>(gat_bias, Whead, p_cbias, HD, N_OUT, bhead);
    gevm<<<N_OUT / 64, 256, 0, s1>>>(p_bsrc, Whead, p_bconst, HD, N_OUT, nullptr);
    cudaEventRecord(ev_csr, s1);

    // ---- default: api logit path + fused fp16 conversion ----
    k_hdot<<<192, 256>>>(Wsrc, attn_l, p_vli);
    k_mat3<<<192, 256>>>(Wapi, p_vli, p_Vl);
    k_b3<<<1, 128>>>(bapi, p_vli, p_bl);
    k_embel<<<N_API / 8, 256>>>(emb_api, p_Vl, p_bl);

    // ---- s3: Wcomb -> W2 -> w2t ----
    sgemm<<<dim3(HD / BN, N_INP / BM, 1), 256, 0, s3>>>(
        Wapi, N_INP, Wsrc, HD, p_Wcomb, HD, N_INP, HD, N_INP, 0, 0, 0);
    sgemm<<<dim3(N_OUT / BN, N_INP / BM, NH), 256, 0, s3>>>(
        p_Wcomb, HD, Whead, N_OUT, p_W2, N_OUT,
        N_INP, N_OUT, N_OUT,
        (long)N_OUT, (long)N_OUT * N_OUT, (long)N_INP * N_OUT);
    k_w2t<<<dim3(N_OUT / 32, KAGG / 32), dim3(32, 8), 0, s3>>>();

    // ---- s2: er path only (agg gate) ----
    k_hdot<<<192, 256, 0, s2>>>(Wdst, attn_r, p_u);
    k_mat3<<<192, 256, 0, s2>>>(Wfile, p_u, p_Vr);
    k_b3<<<1, 128, 0, s2>>>(bfile, p_u, p_br);
    node_logits<<<(N_FILE + 7) / 8, 256, 0, s2>>>(emb_file, p_Vr, p_br, p_er, N_FILE);
    cudaEventRecord(ev_s2, s2);

    // ---- default: aggregation chunks (asymmetric 106/51) ----
    cudaStreamWaitEvent(0, ev_csr, 0);
    cudaStreamWaitEvent(0, ev_s2, 0);
    gat_aggregate<<<CH0_DST, 128>>>(0);
    cudaEventRecord(ev_a0, 0);
    gat_aggregate<<<CH1_DST, 128>>>(CH0_DST);
    cudaEventRecord(ev_a1, 0);

    // ---- s3: gemm chunks ----
    cudaStreamWaitEvent(s3, ev_csr, 0);
    cudaStreamWaitEvent(s3, ev_s2, 0);
    cudaStreamWaitEvent(s3, ev_a0, 0);
    gemm_mma<<<dim3(N_OUT / 128, CH0_BLOCKS), 256, GEMM_SMEM_BYTES, s3>>>(
        p_aggh, p_W2Th, out, p_cbias, p_bconst, p_hasedge, 0);
    cudaStreamWaitEvent(s3, ev_a1, 0);
    gemm_mma<<<dim3(N_OUT / 128, CH1_BLOCKS), 256, GEMM_SMEM_BYTES, s3>>>(
        p_aggh, p_W2Th, out, p_cbias, p_bconst, p_hasedge, CH0_BLOCKS);
    cudaEventRecord(ev_done, s3);

    // join
    cudaStreamWaitEvent(0, ev_done, 0);
}